// round 1
// baseline (speedup 1.0000x reference)
#include <cuda_runtime.h>

#define D 1024
#define HEADS 16
#define DKH 64

// Scratch (allocation-free rule): Q, K, V projections + attention context
__device__ __align__(16) float g_Q[2 * 2048 * 1024];
__device__ __align__(16) float g_K[2 * 2048 * 1024];
__device__ __align__(16) float g_V[2 * 2048 * 1024];
__device__ __align__(16) float g_C[2 * 2048 * 1024];

// ---------- Blackwell packed fp32 helpers (FFMA2 path) ----------
__device__ __forceinline__ unsigned long long fma2(unsigned long long a,
                                                   unsigned long long b,
                                                   unsigned long long c) {
    unsigned long long d;
    asm("fma.rn.f32x2 %0, %1, %2, %3;" : "=l"(d) : "l"(a), "l"(b), "l"(c));
    return d;
}
__device__ __forceinline__ unsigned long long mul2(unsigned long long a,
                                                   unsigned long long b) {
    unsigned long long d;
    asm("mul.rn.f32x2 %0, %1, %2;" : "=l"(d) : "l"(a), "l"(b));
    return d;
}
__device__ __forceinline__ unsigned long long add2(unsigned long long a,
                                                   unsigned long long b) {
    unsigned long long d;
    asm("add.rn.f32x2 %0, %1, %2;" : "=l"(d) : "l"(a), "l"(b));
    return d;
}
__device__ __forceinline__ unsigned long long rep2(float x) {
    unsigned long long r;
    asm("mov.b64 %0, {%1, %1};" : "=l"(r) : "f"(x));
    return r;
}
__device__ __forceinline__ float2 unpack2(unsigned long long v) {
    float2 f;
    asm("mov.b64 {%0, %1}, %2;" : "=f"(f.x), "=f"(f.y) : "l"(v));
    return f;
}

union F4U {
    float4 f;
    unsigned long long u[2];
};

// ---------------------------------------------------------------
// C[m,n] = sum_k A[m,k] * W[n,k] (+ bias[n])   (x @ W^T, torch Linear)
// 128x128 block tile, K-step 8, 256 threads, 8x8 micro-tile via f32x2.
// ---------------------------------------------------------------
__global__ __launch_bounds__(256) void gemm_nt_kernel(
    const float* __restrict__ A, const float* __restrict__ W,
    const float* __restrict__ bias, float* __restrict__ C,
    int M, int N, int K) {
    __shared__ float As[8][132];
    __shared__ float Bs[8][132];

    const int tid = threadIdx.x;
    const int tx = tid & 15;
    const int ty = tid >> 4;
    const int bm = blockIdx.y * 128;
    const int bn = blockIdx.x * 128;

    const int lrow = tid >> 1;        // 0..127
    const int lk = (tid & 1) * 4;     // 0 or 4

    const float* Ap = A + (size_t)(bm + lrow) * K + lk;
    const float* Wp = W + (size_t)(bn + lrow) * K + lk;

    float4 ra = *(const float4*)Ap;
    float4 rb = *(const float4*)Wp;

    unsigned long long acc[8][4];
#pragma unroll
    for (int i = 0; i < 8; i++)
#pragma unroll
        for (int j = 0; j < 4; j++) acc[i][j] = 0ull;

    for (int kt = 0; kt < K; kt += 8) {
        As[lk + 0][lrow] = ra.x;
        As[lk + 1][lrow] = ra.y;
        As[lk + 2][lrow] = ra.z;
        As[lk + 3][lrow] = ra.w;
        Bs[lk + 0][lrow] = rb.x;
        Bs[lk + 1][lrow] = rb.y;
        Bs[lk + 2][lrow] = rb.z;
        Bs[lk + 3][lrow] = rb.w;
        __syncthreads();
        if (kt + 8 < K) {  // prefetch next slab into registers
            ra = *(const float4*)(Ap + kt + 8);
            rb = *(const float4*)(Wp + kt + 8);
        }
#pragma unroll
        for (int kk = 0; kk < 8; kk++) {
            float4 a0 = *(const float4*)&As[kk][ty * 4];
            float4 a1 = *(const float4*)&As[kk][64 + ty * 4];
            F4U b0, b1;
            b0.f = *(const float4*)&Bs[kk][tx * 4];
            b1.f = *(const float4*)&Bs[kk][64 + tx * 4];
            unsigned long long bp[4] = {b0.u[0], b0.u[1], b1.u[0], b1.u[1]};
            float af[8] = {a0.x, a0.y, a0.z, a0.w, a1.x, a1.y, a1.z, a1.w};
            unsigned long long ar[8];
#pragma unroll
            for (int i = 0; i < 8; i++) ar[i] = rep2(af[i]);
#pragma unroll
            for (int i = 0; i < 8; i++)
#pragma unroll
                for (int j = 0; j < 4; j++)
                    acc[i][j] = fma2(ar[i], bp[j], acc[i][j]);
        }
        __syncthreads();
    }

#pragma unroll
    for (int i = 0; i < 8; i++) {
        int row = bm + ((i < 4) ? (ty * 4 + i) : (64 + ty * 4 + (i - 4)));
#pragma unroll
        for (int h = 0; h < 2; h++) {
            int col = bn + ((h == 0) ? (tx * 4) : (64 + tx * 4));
            float2 p0 = unpack2(acc[i][h * 2 + 0]);
            float2 p1 = unpack2(acc[i][h * 2 + 1]);
            float4 o = make_float4(p0.x, p0.y, p1.x, p1.y);
            if (bias) {
                float4 bv = *(const float4*)(bias + col);
                o.x += bv.x;
                o.y += bv.y;
                o.z += bv.z;
                o.w += bv.w;
            }
            *(float4*)(C + (size_t)row * N + col) = o;
        }
    }
}

// ---------------------------------------------------------------
// Flash attention, fp32, 1 thread = 1 query row (dk=64 in regs as pairs).
// Block: 128 threads = 128 q rows. K/V tiled 64 keys at a time in smem.
// Grid: (S/128, HEADS, B). Online softmax, warp-voted rescale.
// ---------------------------------------------------------------
__global__ __launch_bounds__(128) void attn_kernel(
    const float* __restrict__ Qm, const float* __restrict__ Km,
    const float* __restrict__ Vm, float* __restrict__ O, int S) {
    __shared__ float Kt[64][64];
    __shared__ float Vt[64][64];

    const int tid = threadIdx.x;
    const int h = blockIdx.y;
    const int b = blockIdx.z;
    const int q = blockIdx.x * 128 + tid;

    const size_t baseQ = ((size_t)b * S + q) * D + (size_t)h * DKH;

    unsigned long long qp[32];
    {
        const float4* qs = (const float4*)(Qm + baseQ);
#pragma unroll
        for (int i = 0; i < 16; i++) {
            F4U t;
            t.f = qs[i];
            t.f.x *= 0.125f;  // 1/sqrt(dk)
            t.f.y *= 0.125f;
            t.f.z *= 0.125f;
            t.f.w *= 0.125f;
            qp[2 * i] = t.u[0];
            qp[2 * i + 1] = t.u[1];
        }
    }

    unsigned long long accp[32];
#pragma unroll
    for (int i = 0; i < 32; i++) accp[i] = 0ull;
    float m = -1e30f, l = 0.0f;

    const int lrow0 = tid >> 4;        // 0..7
    const int lcol = (tid & 15) * 4;   // 0..60

    for (int kt = 0; kt < S; kt += 64) {
#pragma unroll
        for (int p = 0; p < 8; p++) {
            int r = p * 8 + lrow0;
            size_t g = ((size_t)b * S + kt + r) * D + (size_t)h * DKH + lcol;
            *(float4*)&Kt[r][lcol] = *(const float4*)(Km + g);
            *(float4*)&Vt[r][lcol] = *(const float4*)(Vm + g);
        }
        __syncthreads();

        for (int j = 0; j < 64; j++) {
            const F4U* kr = (const F4U*)&Kt[j][0];
            unsigned long long s0 = 0ull, s1 = 0ull, s2 = 0ull, s3 = 0ull;
#pragma unroll
            for (int i = 0; i < 4; i++) {
                F4U k0 = kr[4 * i + 0];
                F4U k1 = kr[4 * i + 1];
                F4U k2 = kr[4 * i + 2];
                F4U k3 = kr[4 * i + 3];
                s0 = fma2(qp[8 * i + 0], k0.u[0], s0);
                s0 = fma2(qp[8 * i + 1], k0.u[1], s0);
                s1 = fma2(qp[8 * i + 2], k1.u[0], s1);
                s1 = fma2(qp[8 * i + 3], k1.u[1], s1);
                s2 = fma2(qp[8 * i + 4], k2.u[0], s2);
                s2 = fma2(qp[8 * i + 5], k2.u[1], s2);
                s3 = fma2(qp[8 * i + 6], k3.u[0], s3);
                s3 = fma2(qp[8 * i + 7], k3.u[1], s3);
            }
            unsigned long long st = add2(add2(s0, s1), add2(s2, s3));
            float2 sf = unpack2(st);
            float s = sf.x + sf.y;

            float mn = fmaxf(m, s);
            float p = __expf(s - mn);
            float corr = __expf(m - mn);  // == 1.0 exactly when m unchanged
            l = l * corr + p;
            if (__any_sync(0xffffffffu, mn > m)) {
                unsigned long long c2 = rep2(corr);
#pragma unroll
                for (int i = 0; i < 32; i++) accp[i] = mul2(accp[i], c2);
            }
            m = mn;

            unsigned long long p2 = rep2(p);
            const F4U* vr = (const F4U*)&Vt[j][0];
#pragma unroll
            for (int i = 0; i < 16; i++) {
                F4U v = vr[i];
                accp[2 * i] = fma2(p2, v.u[0], accp[2 * i]);
                accp[2 * i + 1] = fma2(p2, v.u[1], accp[2 * i + 1]);
            }
        }
        __syncthreads();
    }

    float inv = 1.0f / l;
    unsigned long long inv2 = rep2(inv);
    float4* Op = (float4*)(O + baseQ);  // ctx written in concat layout [B,S,H*dk]
#pragma unroll
    for (int i = 0; i < 16; i++) {
        F4U o;
        o.u[0] = mul2(accp[2 * i], inv2);
        o.u[1] = mul2(accp[2 * i + 1], inv2);
        Op[i] = o.f;
    }
}

extern "C" void kernel_launch(void* const* d_in, const int* in_sizes, int n_in,
                              void* d_out, int out_size) {
    const float* key = (const float*)d_in[0];
    const float* query = (const float*)d_in[1];
    const float* value = (const float*)d_in[2];
    const float* Wq = (const float*)d_in[3];
    const float* Wk = (const float*)d_in[4];
    const float* Wv = (const float*)d_in[5];
    const float* Wo = (const float*)d_in[6];
    const float* bo = (const float*)d_in[7];

    const int B = 2;
    const int S = in_sizes[0] / (B * D);  // 2048
    const int M = B * S;                  // 4096

    float *Qb, *Kb, *Vb, *Cb;
    cudaGetSymbolAddress((void**)&Qb, g_Q);
    cudaGetSymbolAddress((void**)&Kb, g_K);
    cudaGetSymbolAddress((void**)&Vb, g_V);
    cudaGetSymbolAddress((void**)&Cb, g_C);

    dim3 gB(D / 128, M / 128);  // (8, 32)
    gemm_nt_kernel<<<gB, 256>>>(query, Wq, nullptr, Qb, M, D, D);
    gemm_nt_kernel<<<gB, 256>>>(key, Wk, nullptr, Kb, M, D, D);
    gemm_nt_kernel<<<gB, 256>>>(value, Wv, nullptr, Vb, M, D, D);

    dim3 gA(S / 128, HEADS, B);
    attn_kernel<<<gA, 128>>>(Qb, Kb, Vb, Cb, S);

    gemm_nt_kernel<<<gB, 256>>>(Cb, Wo, bo, (float*)d_out, M, D, D);
}

// round 4
// speedup vs baseline: 1.1277x; 1.1277x over previous
#include <cuda_runtime.h>
#include <cuda_bf16.h>
#include <stdint.h>

#define D 1024
#define HEADS 16
#define DKH 64
#define KP 3072            // split-K' = 3 x 1024
#define LDAB 40            // smem row stride in bf16 (80B, 16B-aligned, conflict-free)
#define NSTAGE 4
#define STAGE_BYTES 20480  // A(128x40x2) + B(128x40x2)
#define GSMEM (NSTAGE * STAGE_BYTES)

// ---------------- scratch (allocation-free rule) ----------------
__device__ __align__(16) float g_Q[2 * 2048 * 1024];
__device__ __align__(16) float g_K[2 * 2048 * 1024];
__device__ __align__(16) float g_V[2 * 2048 * 1024];
__device__ __align__(16) float g_C[2 * 2048 * 1024];
__device__ __align__(16) __nv_bfloat16 g_As[4096 * KP];  // [M, 3K] split A
__device__ __align__(16) __nv_bfloat16 g_Ws[1024 * KP];  // [N, 3K] split W

// ---------------- PTX helpers (plain sm_103 ISA only) ----------------
__device__ __forceinline__ uint32_t smem_u32(const void* p) {
    uint32_t a;
    asm("{ .reg .u64 t; cvta.to.shared.u64 t, %1; cvt.u32.u64 %0, t; }" : "=r"(a) : "l"(p));
    return a;
}
__device__ __forceinline__ void cp16(uint32_t dst, const void* src) {
    asm volatile("cp.async.cg.shared.global [%0], [%1], 16;\n" :: "r"(dst), "l"(src) : "memory");
}
#define CP_COMMIT() asm volatile("cp.async.commit_group;\n" ::: "memory")
#define CP_WAIT(n) asm volatile("cp.async.wait_group %0;\n" :: "n"(n) : "memory")

__device__ __forceinline__ void ldsm_x4(uint32_t& r0, uint32_t& r1, uint32_t& r2, uint32_t& r3, uint32_t addr) {
    asm volatile("ldmatrix.sync.aligned.m8n8.x4.shared.b16 {%0,%1,%2,%3}, [%4];"
                 : "=r"(r0), "=r"(r1), "=r"(r2), "=r"(r3) : "r"(addr));
}
__device__ __forceinline__ void mma_bf16(float* c, uint32_t a0, uint32_t a1, uint32_t a2, uint32_t a3,
                                         uint32_t b0, uint32_t b1) {
    asm volatile(
        "mma.sync.aligned.m16n8k16.row.col.f32.bf16.bf16.f32 "
        "{%0,%1,%2,%3}, {%4,%5,%6,%7}, {%8,%9}, {%0,%1,%2,%3};"
        : "+f"(c[0]), "+f"(c[1]), "+f"(c[2]), "+f"(c[3])
        : "r"(a0), "r"(a1), "r"(a2), "r"(a3), "r"(b0), "r"(b1));
}

// ---------------- fp32 -> bf16 hi/lo 3-segment split ----------------
// mode 0 (activations): [hi | hi | lo]   mode 1 (weights): [hi | lo | hi]
// => sum over K'=3072 yields Ahi*Bhi + Ahi*Blo + Alo*Bhi
union B4 { __nv_bfloat162 h2[2]; uint2 u; };

__global__ __launch_bounds__(256) void split3(const float* __restrict__ x,
                                              __nv_bfloat16* __restrict__ out,
                                              int n, int mode) {
    int i = (blockIdx.x * 256 + threadIdx.x) * 4;
    if (i >= n) return;
    float4 v = *(const float4*)(x + i);
    __nv_bfloat16 h0 = __float2bfloat16(v.x), h1 = __float2bfloat16(v.y);
    __nv_bfloat16 h2 = __float2bfloat16(v.z), h3 = __float2bfloat16(v.w);
    __nv_bfloat16 l0 = __float2bfloat16(v.x - __bfloat162float(h0));
    __nv_bfloat16 l1 = __float2bfloat16(v.y - __bfloat162float(h1));
    __nv_bfloat16 l2 = __float2bfloat16(v.z - __bfloat162float(h2));
    __nv_bfloat16 l3 = __float2bfloat16(v.w - __bfloat162float(h3));
    B4 hv, lv;
    hv.h2[0] = __nv_bfloat162(h0, h1); hv.h2[1] = __nv_bfloat162(h2, h3);
    lv.h2[0] = __nv_bfloat162(l0, l1); lv.h2[1] = __nv_bfloat162(l2, l3);
    int row = i >> 10, col = i & 1023;
    size_t base = (size_t)row * KP + col;
    *(uint2*)(out + base) = hv.u;
    if (mode == 0) {
        *(uint2*)(out + base + 1024) = hv.u;
        *(uint2*)(out + base + 2048) = lv.u;
    } else {
        *(uint2*)(out + base + 1024) = lv.u;
        *(uint2*)(out + base + 2048) = hv.u;
    }
}

// ---------------- bf16 mma.sync GEMM: C[M,1024] = A'[M,3072] @ W'[1024,3072]^T (+bias)
// 128x128 CTA tile, BK=32, 256 threads, 4-stage cp.async pipeline.
__device__ __forceinline__ void load_stage(uint32_t sm, const __nv_bfloat16* A,
                                           const __nv_bfloat16* B, int bm, int bn,
                                           int it, int tid) {
    size_t kof = (size_t)it * 32;
#pragma unroll
    for (int i = 0; i < 2; i++) {
        int c = tid + 256 * i;
        int r = c >> 2, kc = (c & 3) * 8;
        cp16(sm + (r * LDAB + kc) * 2, A + (size_t)(bm + r) * KP + kof + kc);
    }
#pragma unroll
    for (int i = 0; i < 2; i++) {
        int c = tid + 256 * i;
        int r = c >> 2, kc = (c & 3) * 8;
        cp16(sm + 10240 + (r * LDAB + kc) * 2, B + (size_t)(bn + r) * KP + kof + kc);
    }
}

__global__ __launch_bounds__(256, 1) void gemm_mma(
    const __nv_bfloat16* __restrict__ A, const __nv_bfloat16* __restrict__ W,
    const float* __restrict__ bias, float* __restrict__ C) {
    extern __shared__ char smem[];
    const uint32_t sb = smem_u32(smem);
    const int tid = threadIdx.x;
    const int wid = tid >> 5;
    const int l = tid & 31;
    const int warp_m = wid >> 1;   // 0..3
    const int warp_n = wid & 1;    // 0..1
    const int bm = blockIdx.y * 128;
    const int bn = blockIdx.x * 128;
    const int NIT = KP / 32;       // 96

    float acc[2][8][4];
#pragma unroll
    for (int mi = 0; mi < 2; mi++)
#pragma unroll
        for (int ni = 0; ni < 8; ni++)
#pragma unroll
            for (int r = 0; r < 4; r++) acc[mi][ni][r] = 0.0f;

    // ldmatrix lane addressing (b16 element offsets)
    const int a_row = warp_m * 32 + (l & 15);
    const int a_ko = (l >> 4) << 3;
    const int b_row = warp_n * 64 + ((l >> 4) << 3) + (l & 7);
    const int b_ko = ((l >> 3) & 1) << 3;

    // prologue: stages 0..NSTAGE-2
#pragma unroll
    for (int s = 0; s < NSTAGE - 1; s++) {
        load_stage(sb + s * STAGE_BYTES, A, W, bm, bn, s, tid);
        CP_COMMIT();
    }

    for (int it = 0; it < NIT; it++) {
        CP_WAIT(NSTAGE - 2);
        __syncthreads();
        // issue next stage (overlaps with compute below)
        if (it + NSTAGE - 1 < NIT)
            load_stage(sb + ((it + NSTAGE - 1) % NSTAGE) * STAGE_BYTES, A, W, bm, bn,
                       it + NSTAGE - 1, tid);
        CP_COMMIT();

        const uint32_t sA = sb + (it % NSTAGE) * STAGE_BYTES;
        const uint32_t sB = sA + 10240;
#pragma unroll
        for (int kk = 0; kk < 2; kk++) {
            const int kcol = kk * 16;
            uint32_t aF[2][4];
#pragma unroll
            for (int mi = 0; mi < 2; mi++)
                ldsm_x4(aF[mi][0], aF[mi][1], aF[mi][2], aF[mi][3],
                        sA + ((a_row + mi * 16) * LDAB + kcol + a_ko) * 2);
            uint32_t bF[8][2];
#pragma unroll
            for (int p = 0; p < 4; p++) {
                uint32_t r0, r1, r2, r3;
                ldsm_x4(r0, r1, r2, r3,
                        sB + ((b_row + p * 16) * LDAB + kcol + b_ko) * 2);
                bF[2 * p][0] = r0; bF[2 * p][1] = r1;
                bF[2 * p + 1][0] = r2; bF[2 * p + 1][1] = r3;
            }
#pragma unroll
            for (int mi = 0; mi < 2; mi++)
#pragma unroll
                for (int ni = 0; ni < 8; ni++)
                    mma_bf16(acc[mi][ni], aF[mi][0], aF[mi][1], aF[mi][2], aF[mi][3],
                             bF[ni][0], bF[ni][1]);
        }
    }

    // epilogue: per-thread fragment writeback (float2 stores)
    const int tr = l >> 2;         // 0..7
    const int tc = (l & 3) * 2;    // 0,2,4,6
#pragma unroll
    for (int mi = 0; mi < 2; mi++) {
#pragma unroll
        for (int ni = 0; ni < 8; ni++) {
            int row0 = bm + warp_m * 32 + mi * 16 + tr;
            int col = bn + warp_n * 64 + ni * 8 + tc;
            float2 v0 = make_float2(acc[mi][ni][0], acc[mi][ni][1]);
            float2 v1 = make_float2(acc[mi][ni][2], acc[mi][ni][3]);
            if (bias) {
                float2 bv = *(const float2*)(bias + col);
                v0.x += bv.x; v0.y += bv.y;
                v1.x += bv.x; v1.y += bv.y;
            }
            *(float2*)(C + (size_t)row0 * 1024 + col) = v0;
            *(float2*)(C + (size_t)(row0 + 8) * 1024 + col) = v1;
        }
    }
}

// ---------------- flash attention (unchanged, fp32 f32x2 path) ----------------
__device__ __forceinline__ unsigned long long fma2(unsigned long long a, unsigned long long b, unsigned long long c) {
    unsigned long long d;
    asm("fma.rn.f32x2 %0, %1, %2, %3;" : "=l"(d) : "l"(a), "l"(b), "l"(c));
    return d;
}
__device__ __forceinline__ unsigned long long mul2(unsigned long long a, unsigned long long b) {
    unsigned long long d;
    asm("mul.rn.f32x2 %0, %1, %2;" : "=l"(d) : "l"(a), "l"(b));
    return d;
}
__device__ __forceinline__ unsigned long long add2(unsigned long long a, unsigned long long b) {
    unsigned long long d;
    asm("add.rn.f32x2 %0, %1, %2;" : "=l"(d) : "l"(a), "l"(b));
    return d;
}
__device__ __forceinline__ unsigned long long rep2(float x) {
    unsigned long long r;
    asm("mov.b64 %0, {%1, %1};" : "=l"(r) : "f"(x));
    return r;
}
__device__ __forceinline__ float2 unpack2(unsigned long long v) {
    float2 f;
    asm("mov.b64 {%0, %1}, %2;" : "=f"(f.x), "=f"(f.y) : "l"(v));
    return f;
}
union F4U {
    float4 f;
    unsigned long long u[2];
};

__global__ __launch_bounds__(128) void attn_kernel(
    const float* __restrict__ Qm, const float* __restrict__ Km,
    const float* __restrict__ Vm, float* __restrict__ O, int S) {
    __shared__ float Kt[64][64];
    __shared__ float Vt[64][64];

    const int tid = threadIdx.x;
    const int h = blockIdx.y;
    const int b = blockIdx.z;
    const int q = blockIdx.x * 128 + tid;
    const size_t baseQ = ((size_t)b * S + q) * D + (size_t)h * DKH;

    unsigned long long qp[32];
    {
        const float4* qs = (const float4*)(Qm + baseQ);
#pragma unroll
        for (int i = 0; i < 16; i++) {
            F4U t;
            t.f = qs[i];
            t.f.x *= 0.125f; t.f.y *= 0.125f; t.f.z *= 0.125f; t.f.w *= 0.125f;
            qp[2 * i] = t.u[0];
            qp[2 * i + 1] = t.u[1];
        }
    }

    unsigned long long accp[32];
#pragma unroll
    for (int i = 0; i < 32; i++) accp[i] = 0ull;
    float m = -1e30f, lsum = 0.0f;

    const int lrow0 = tid >> 4;
    const int lcol = (tid & 15) * 4;

    for (int kt = 0; kt < S; kt += 64) {
#pragma unroll
        for (int p = 0; p < 8; p++) {
            int r = p * 8 + lrow0;
            size_t g = ((size_t)b * S + kt + r) * D + (size_t)h * DKH + lcol;
            *(float4*)&Kt[r][lcol] = *(const float4*)(Km + g);
            *(float4*)&Vt[r][lcol] = *(const float4*)(Vm + g);
        }
        __syncthreads();

        for (int j = 0; j < 64; j++) {
            const F4U* kr = (const F4U*)&Kt[j][0];
            unsigned long long s0 = 0ull, s1 = 0ull, s2 = 0ull, s3 = 0ull;
#pragma unroll
            for (int i = 0; i < 4; i++) {
                F4U k0 = kr[4 * i + 0];
                F4U k1 = kr[4 * i + 1];
                F4U k2 = kr[4 * i + 2];
                F4U k3 = kr[4 * i + 3];
                s0 = fma2(qp[8 * i + 0], k0.u[0], s0);
                s0 = fma2(qp[8 * i + 1], k0.u[1], s0);
                s1 = fma2(qp[8 * i + 2], k1.u[0], s1);
                s1 = fma2(qp[8 * i + 3], k1.u[1], s1);
                s2 = fma2(qp[8 * i + 4], k2.u[0], s2);
                s2 = fma2(qp[8 * i + 5], k2.u[1], s2);
                s3 = fma2(qp[8 * i + 6], k3.u[0], s3);
                s3 = fma2(qp[8 * i + 7], k3.u[1], s3);
            }
            unsigned long long st = add2(add2(s0, s1), add2(s2, s3));
            float2 sf = unpack2(st);
            float s = sf.x + sf.y;

            float mn = fmaxf(m, s);
            float p = __expf(s - mn);
            float corr = __expf(m - mn);
            lsum = lsum * corr + p;
            if (__any_sync(0xffffffffu, mn > m)) {
                unsigned long long c2 = rep2(corr);
#pragma unroll
                for (int i = 0; i < 32; i++) accp[i] = mul2(accp[i], c2);
            }
            m = mn;

            unsigned long long p2 = rep2(p);
            const F4U* vr = (const F4U*)&Vt[j][0];
#pragma unroll
            for (int i = 0; i < 16; i++) {
                F4U v = vr[i];
                accp[2 * i] = fma2(p2, v.u[0], accp[2 * i]);
                accp[2 * i + 1] = fma2(p2, v.u[1], accp[2 * i + 1]);
            }
        }
        __syncthreads();
    }

    float inv = 1.0f / lsum;
    unsigned long long inv2 = rep2(inv);
    float4* Op = (float4*)(O + baseQ);
#pragma unroll
    for (int i = 0; i < 16; i++) {
        F4U o;
        o.u[0] = mul2(accp[2 * i], inv2);
        o.u[1] = mul2(accp[2 * i + 1], inv2);
        Op[i] = o.f;
    }
}

// ---------------- launch ----------------
extern "C" void kernel_launch(void* const* d_in, const int* in_sizes, int n_in,
                              void* d_out, int out_size) {
    const float* key = (const float*)d_in[0];
    const float* query = (const float*)d_in[1];
    const float* value = (const float*)d_in[2];
    const float* Wq = (const float*)d_in[3];
    const float* Wk = (const float*)d_in[4];
    const float* Wv = (const float*)d_in[5];
    const float* Wo = (const float*)d_in[6];
    const float* bo = (const float*)d_in[7];

    const int B = 2;
    const int S = in_sizes[0] / (B * D);  // 2048
    const int M = B * S;                  // 4096
    const int nA = M * D;
    const int nW = D * D;

    float *Qb, *Kb, *Vb, *Cb;
    __nv_bfloat16 *As, *Ws;
    cudaGetSymbolAddress((void**)&Qb, g_Q);
    cudaGetSymbolAddress((void**)&Kb, g_K);
    cudaGetSymbolAddress((void**)&Vb, g_V);
    cudaGetSymbolAddress((void**)&Cb, g_C);
    cudaGetSymbolAddress((void**)&As, g_As);
    cudaGetSymbolAddress((void**)&Ws, g_Ws);

    cudaFuncSetAttribute(gemm_mma, cudaFuncAttributeMaxDynamicSharedMemorySize, GSMEM);

    dim3 gG(D / 128, M / 128);  // (8, 32)
    const int gA = nA / 1024, gW = nW / 1024;

    split3<<<gA, 256>>>(query, As, nA, 0);
    split3<<<gW, 256>>>(Wq, Ws, nW, 1);
    gemm_mma<<<gG, 256, GSMEM>>>(As, Ws, nullptr, Qb);

    split3<<<gA, 256>>>(key, As, nA, 0);
    split3<<<gW, 256>>>(Wk, Ws, nW, 1);
    gemm_mma<<<gG, 256, GSMEM>>>(As, Ws, nullptr, Kb);

    split3<<<gA, 256>>>(value, As, nA, 0);
    split3<<<gW, 256>>>(Wv, Ws, nW, 1);
    gemm_mma<<<gG, 256, GSMEM>>>(As, Ws, nullptr, Vb);

    dim3 gAt(S / 128, HEADS, B);
    attn_kernel<<<gAt, 128>>>(Qb, Kb, Vb, Cb, S);

    split3<<<gA, 256>>>(Cb, As, nA, 0);
    split3<<<gW, 256>>>(Wo, Ws, nW, 1);
    gemm_mma<<<gG, 256, GSMEM>>>(As, Ws, bo, (float*)d_out);
}

// round 5
// speedup vs baseline: 1.1835x; 1.0495x over previous
#include <cuda_runtime.h>
#include <cuda_bf16.h>
#include <stdint.h>

#define D 1024
#define HEADS 16
#define DKH 64
#define KP 3072            // split-K' = 3 x 1024
#define LDAB 40            // smem row stride in bf16 (80B, 16B-aligned, conflict-free)
#define NSTAGE 3
#define STAGE_BYTES 20480  // A(128x40x2) + B(128x40x2)
#define GSMEM (NSTAGE * STAGE_BYTES)

// ---------------- scratch (allocation-free rule) ----------------
__device__ __align__(16) float g_Q[2 * 2048 * 1024];
__device__ __align__(16) float g_K[2 * 2048 * 1024];
__device__ __align__(16) float g_V[2 * 2048 * 1024];
__device__ __align__(16) float g_C[2 * 2048 * 1024];
__device__ __align__(16) __nv_bfloat16 g_As[4096 * KP];  // [M, 3K] split A
__device__ __align__(16) __nv_bfloat16 g_Ws[1024 * KP];  // [N, 3K] split W

// ---------------- PTX helpers (plain sm_103 ISA only) ----------------
__device__ __forceinline__ uint32_t smem_u32(const void* p) {
    uint32_t a;
    asm("{ .reg .u64 t; cvta.to.shared.u64 t, %1; cvt.u32.u64 %0, t; }" : "=r"(a) : "l"(p));
    return a;
}
__device__ __forceinline__ void cp16(uint32_t dst, const void* src) {
    asm volatile("cp.async.cg.shared.global [%0], [%1], 16;\n" :: "r"(dst), "l"(src) : "memory");
}
#define CP_COMMIT() asm volatile("cp.async.commit_group;\n" ::: "memory")
#define CP_WAIT(n) asm volatile("cp.async.wait_group %0;\n" :: "n"(n) : "memory")

__device__ __forceinline__ void ldsm_x4(uint32_t& r0, uint32_t& r1, uint32_t& r2, uint32_t& r3, uint32_t addr) {
    asm volatile("ldmatrix.sync.aligned.m8n8.x4.shared.b16 {%0,%1,%2,%3}, [%4];"
                 : "=r"(r0), "=r"(r1), "=r"(r2), "=r"(r3) : "r"(addr));
}
__device__ __forceinline__ void mma_bf16(float* c, uint32_t a0, uint32_t a1, uint32_t a2, uint32_t a3,
                                         uint32_t b0, uint32_t b1) {
    asm volatile(
        "mma.sync.aligned.m16n8k16.row.col.f32.bf16.bf16.f32 "
        "{%0,%1,%2,%3}, {%4,%5,%6,%7}, {%8,%9}, {%0,%1,%2,%3};"
        : "+f"(c[0]), "+f"(c[1]), "+f"(c[2]), "+f"(c[3])
        : "r"(a0), "r"(a1), "r"(a2), "r"(a3), "r"(b0), "r"(b1));
}

// ---------------- fp32 -> bf16 hi/lo 3-segment split ----------------
// mode 0 (activations): [hi | hi | lo]   mode 1 (weights): [hi | lo | hi]
// => sum over K'=3072 yields Ahi*Bhi + Ahi*Blo + Alo*Bhi
union B4 { __nv_bfloat162 h2[2]; uint2 u; };

__global__ __launch_bounds__(256) void split3(const float* __restrict__ x,
                                              __nv_bfloat16* __restrict__ out,
                                              int n, int mode) {
    int i = (blockIdx.x * 256 + threadIdx.x) * 4;
    if (i >= n) return;
    float4 v = *(const float4*)(x + i);
    __nv_bfloat16 h0 = __float2bfloat16(v.x), h1 = __float2bfloat16(v.y);
    __nv_bfloat16 h2 = __float2bfloat16(v.z), h3 = __float2bfloat16(v.w);
    __nv_bfloat16 l0 = __float2bfloat16(v.x - __bfloat162float(h0));
    __nv_bfloat16 l1 = __float2bfloat16(v.y - __bfloat162float(h1));
    __nv_bfloat16 l2 = __float2bfloat16(v.z - __bfloat162float(h2));
    __nv_bfloat16 l3 = __float2bfloat16(v.w - __bfloat162float(h3));
    B4 hv, lv;
    hv.h2[0] = __nv_bfloat162(h0, h1); hv.h2[1] = __nv_bfloat162(h2, h3);
    lv.h2[0] = __nv_bfloat162(l0, l1); lv.h2[1] = __nv_bfloat162(l2, l3);
    int row = i >> 10, col = i & 1023;
    size_t base = (size_t)row * KP + col;
    *(uint2*)(out + base) = hv.u;
    if (mode == 0) {
        *(uint2*)(out + base + 1024) = hv.u;
        *(uint2*)(out + base + 2048) = lv.u;
    } else {
        *(uint2*)(out + base + 1024) = lv.u;
        *(uint2*)(out + base + 2048) = hv.u;
    }
}

// ---------------- bf16 mma.sync GEMM: C[M,1024] = A'[M,3072] @ W'[1024,3072]^T (+bias)
// 128x128 CTA tile, BK=32, 256 threads, 3-stage cp.async pipeline, 2 CTAs/SM.
__device__ __forceinline__ void load_stage(uint32_t sm, const __nv_bfloat16* A,
                                           const __nv_bfloat16* B, int bm, int bn,
                                           int it, int tid) {
    size_t kof = (size_t)it * 32;
#pragma unroll
    for (int i = 0; i < 2; i++) {
        int c = tid + 256 * i;
        int r = c >> 2, kc = (c & 3) * 8;
        cp16(sm + (r * LDAB + kc) * 2, A + (size_t)(bm + r) * KP + kof + kc);
    }
#pragma unroll
    for (int i = 0; i < 2; i++) {
        int c = tid + 256 * i;
        int r = c >> 2, kc = (c & 3) * 8;
        cp16(sm + 10240 + (r * LDAB + kc) * 2, B + (size_t)(bn + r) * KP + kof + kc);
    }
}

__global__ __launch_bounds__(256, 2) void gemm_mma(
    const __nv_bfloat16* __restrict__ A, const __nv_bfloat16* __restrict__ W,
    const float* __restrict__ bias, float* __restrict__ C) {
    extern __shared__ char smem[];
    const uint32_t sb = smem_u32(smem);
    const int tid = threadIdx.x;
    const int wid = tid >> 5;
    const int l = tid & 31;
    const int warp_m = wid >> 1;   // 0..3
    const int warp_n = wid & 1;    // 0..1
    const int bm = blockIdx.y * 128;
    const int bn = blockIdx.x * 128;
    const int NIT = KP / 32;       // 96

    float acc[2][8][4];
#pragma unroll
    for (int mi = 0; mi < 2; mi++)
#pragma unroll
        for (int ni = 0; ni < 8; ni++)
#pragma unroll
            for (int r = 0; r < 4; r++) acc[mi][ni][r] = 0.0f;

    // ldmatrix lane addressing (b16 element offsets)
    const int a_row = warp_m * 32 + (l & 15);
    const int a_ko = (l >> 4) << 3;
    const int b_row = warp_n * 64 + ((l >> 4) << 3) + (l & 7);
    const int b_ko = ((l >> 3) & 1) << 3;

    // prologue: stages 0..NSTAGE-2
#pragma unroll
    for (int s = 0; s < NSTAGE - 1; s++) {
        load_stage(sb + s * STAGE_BYTES, A, W, bm, bn, s, tid);
        CP_COMMIT();
    }

    for (int it = 0; it < NIT; it++) {
        CP_WAIT(NSTAGE - 2);
        __syncthreads();
        // issue next stage (overlaps with compute below)
        if (it + NSTAGE - 1 < NIT)
            load_stage(sb + ((it + NSTAGE - 1) % NSTAGE) * STAGE_BYTES, A, W, bm, bn,
                       it + NSTAGE - 1, tid);
        CP_COMMIT();

        const uint32_t sA = sb + (it % NSTAGE) * STAGE_BYTES;
        const uint32_t sB = sA + 10240;
#pragma unroll
        for (int kk = 0; kk < 2; kk++) {
            const int kcol = kk * 16;
            uint32_t aF[2][4];
#pragma unroll
            for (int mi = 0; mi < 2; mi++)
                ldsm_x4(aF[mi][0], aF[mi][1], aF[mi][2], aF[mi][3],
                        sA + ((a_row + mi * 16) * LDAB + kcol + a_ko) * 2);
            uint32_t bF[8][2];
#pragma unroll
            for (int p = 0; p < 4; p++) {
                uint32_t r0, r1, r2, r3;
                ldsm_x4(r0, r1, r2, r3,
                        sB + ((b_row + p * 16) * LDAB + kcol + b_ko) * 2);
                bF[2 * p][0] = r0; bF[2 * p][1] = r1;
                bF[2 * p + 1][0] = r2; bF[2 * p + 1][1] = r3;
            }
#pragma unroll
            for (int mi = 0; mi < 2; mi++)
#pragma unroll
                for (int ni = 0; ni < 8; ni++)
                    mma_bf16(acc[mi][ni], aF[mi][0], aF[mi][1], aF[mi][2], aF[mi][3],
                             bF[ni][0], bF[ni][1]);
        }
    }

    // epilogue: per-thread fragment writeback (float2 stores)
    const int tr = l >> 2;         // 0..7
    const int tc = (l & 3) * 2;    // 0,2,4,6
#pragma unroll
    for (int mi = 0; mi < 2; mi++) {
#pragma unroll
        for (int ni = 0; ni < 8; ni++) {
            int row0 = bm + warp_m * 32 + mi * 16 + tr;
            int col = bn + warp_n * 64 + ni * 8 + tc;
            float2 v0 = make_float2(acc[mi][ni][0], acc[mi][ni][1]);
            float2 v1 = make_float2(acc[mi][ni][2], acc[mi][ni][3]);
            if (bias) {
                float2 bv = *(const float2*)(bias + col);
                v0.x += bv.x; v0.y += bv.y;
                v1.x += bv.x; v1.y += bv.y;
            }
            *(float2*)(C + (size_t)row0 * 1024 + col) = v0;
            *(float2*)(C + (size_t)(row0 + 8) * 1024 + col) = v1;
        }
    }
}

// ---------------- flash attention (unchanged, fp32 f32x2 path) ----------------
__device__ __forceinline__ unsigned long long fma2(unsigned long long a, unsigned long long b, unsigned long long c) {
    unsigned long long d;
    asm("fma.rn.f32x2 %0, %1, %2, %3;" : "=l"(d) : "l"(a), "l"(b), "l"(c));
    return d;
}
__device__ __forceinline__ unsigned long long mul2(unsigned long long a, unsigned long long b) {
    unsigned long long d;
    asm("mul.rn.f32x2 %0, %1, %2;" : "=l"(d) : "l"(a), "l"(b));
    return d;
}
__device__ __forceinline__ unsigned long long add2(unsigned long long a, unsigned long long b) {
    unsigned long long d;
    asm("add.rn.f32x2 %0, %1, %2;" : "=l"(d) : "l"(a), "l"(b));
    return d;
}
__device__ __forceinline__ unsigned long long rep2(float x) {
    unsigned long long r;
    asm("mov.b64 %0, {%1, %1};" : "=l"(r) : "f"(x));
    return r;
}
__device__ __forceinline__ float2 unpack2(unsigned long long v) {
    float2 f;
    asm("mov.b64 {%0, %1}, %2;" : "=f"(f.x), "=f"(f.y) : "l"(v));
    return f;
}
union F4U {
    float4 f;
    unsigned long long u[2];
};

__global__ __launch_bounds__(128) void attn_kernel(
    const float* __restrict__ Qm, const float* __restrict__ Km,
    const float* __restrict__ Vm, float* __restrict__ O, int S) {
    __shared__ float Kt[64][64];
    __shared__ float Vt[64][64];

    const int tid = threadIdx.x;
    const int h = blockIdx.y;
    const int b = blockIdx.z;
    const int q = blockIdx.x * 128 + tid;
    const size_t baseQ = ((size_t)b * S + q) * D + (size_t)h * DKH;

    unsigned long long qp[32];
    {
        const float4* qs = (const float4*)(Qm + baseQ);
#pragma unroll
        for (int i = 0; i < 16; i++) {
            F4U t;
            t.f = qs[i];
            t.f.x *= 0.125f; t.f.y *= 0.125f; t.f.z *= 0.125f; t.f.w *= 0.125f;
            qp[2 * i] = t.u[0];
            qp[2 * i + 1] = t.u[1];
        }
    }

    unsigned long long accp[32];
#pragma unroll
    for (int i = 0; i < 32; i++) accp[i] = 0ull;
    float m = -1e30f, lsum = 0.0f;

    const int lrow0 = tid >> 4;
    const int lcol = (tid & 15) * 4;

    for (int kt = 0; kt < S; kt += 64) {
#pragma unroll
        for (int p = 0; p < 8; p++) {
            int r = p * 8 + lrow0;
            size_t g = ((size_t)b * S + kt + r) * D + (size_t)h * DKH + lcol;
            *(float4*)&Kt[r][lcol] = *(const float4*)(Km + g);
            *(float4*)&Vt[r][lcol] = *(const float4*)(Vm + g);
        }
        __syncthreads();

        for (int j = 0; j < 64; j++) {
            const F4U* kr = (const F4U*)&Kt[j][0];
            unsigned long long s0 = 0ull, s1 = 0ull, s2 = 0ull, s3 = 0ull;
#pragma unroll
            for (int i = 0; i < 4; i++) {
                F4U k0 = kr[4 * i + 0];
                F4U k1 = kr[4 * i + 1];
                F4U k2 = kr[4 * i + 2];
                F4U k3 = kr[4 * i + 3];
                s0 = fma2(qp[8 * i + 0], k0.u[0], s0);
                s0 = fma2(qp[8 * i + 1], k0.u[1], s0);
                s1 = fma2(qp[8 * i + 2], k1.u[0], s1);
                s1 = fma2(qp[8 * i + 3], k1.u[1], s1);
                s2 = fma2(qp[8 * i + 4], k2.u[0], s2);
                s2 = fma2(qp[8 * i + 5], k2.u[1], s2);
                s3 = fma2(qp[8 * i + 6], k3.u[0], s3);
                s3 = fma2(qp[8 * i + 7], k3.u[1], s3);
            }
            unsigned long long st = add2(add2(s0, s1), add2(s2, s3));
            float2 sf = unpack2(st);
            float s = sf.x + sf.y;

            float mn = fmaxf(m, s);
            float p = __expf(s - mn);
            float corr = __expf(m - mn);
            lsum = lsum * corr + p;
            if (__any_sync(0xffffffffu, mn > m)) {
                unsigned long long c2 = rep2(corr);
#pragma unroll
                for (int i = 0; i < 32; i++) accp[i] = mul2(accp[i], c2);
            }
            m = mn;

            unsigned long long p2 = rep2(p);
            const F4U* vr = (const F4U*)&Vt[j][0];
#pragma unroll
            for (int i = 0; i < 16; i++) {
                F4U v = vr[i];
                accp[2 * i] = fma2(p2, v.u[0], accp[2 * i]);
                accp[2 * i + 1] = fma2(p2, v.u[1], accp[2 * i + 1]);
            }
        }
        __syncthreads();
    }

    float inv = 1.0f / lsum;
    unsigned long long inv2 = rep2(inv);
    float4* Op = (float4*)(O + baseQ);
#pragma unroll
    for (int i = 0; i < 16; i++) {
        F4U o;
        o.u[0] = mul2(accp[2 * i], inv2);
        o.u[1] = mul2(accp[2 * i + 1], inv2);
        Op[i] = o.f;
    }
}

// ---------------- launch ----------------
extern "C" void kernel_launch(void* const* d_in, const int* in_sizes, int n_in,
                              void* d_out, int out_size) {
    const float* key = (const float*)d_in[0];
    const float* query = (const float*)d_in[1];
    const float* value = (const float*)d_in[2];
    const float* Wq = (const float*)d_in[3];
    const float* Wk = (const float*)d_in[4];
    const float* Wv = (const float*)d_in[5];
    const float* Wo = (const float*)d_in[6];
    const float* bo = (const float*)d_in[7];

    const int B = 2;
    const int S = in_sizes[0] / (B * D);  // 2048
    const int M = B * S;                  // 4096
    const int nA = M * D;
    const int nW = D * D;

    float *Qb, *Kb, *Vb, *Cb;
    __nv_bfloat16 *As, *Ws;
    cudaGetSymbolAddress((void**)&Qb, g_Q);
    cudaGetSymbolAddress((void**)&Kb, g_K);
    cudaGetSymbolAddress((void**)&Vb, g_V);
    cudaGetSymbolAddress((void**)&Cb, g_C);
    cudaGetSymbolAddress((void**)&As, g_As);
    cudaGetSymbolAddress((void**)&Ws, g_Ws);

    cudaFuncSetAttribute(gemm_mma, cudaFuncAttributeMaxDynamicSharedMemorySize, GSMEM);

    dim3 gG(D / 128, M / 128);  // (8, 32)
    const int gA = nA / 1024, gW = nW / 1024;

    split3<<<gA, 256>>>(query, As, nA, 0);
    split3<<<gW, 256>>>(Wq, Ws, nW, 1);
    gemm_mma<<<gG, 256, GSMEM>>>(As, Ws, nullptr, Qb);

    split3<<<gA, 256>>>(key, As, nA, 0);
    split3<<<gW, 256>>>(Wk, Ws, nW, 1);
    gemm_mma<<<gG, 256, GSMEM>>>(As, Ws, nullptr, Kb);

    split3<<<gA, 256>>>(value, As, nA, 0);
    split3<<<gW, 256>>>(Wv, Ws, nW, 1);
    gemm_mma<<<gG, 256, GSMEM>>>(As, Ws, nullptr, Vb);

    dim3 gAt(S / 128, HEADS, B);
    attn_kernel<<<gAt, 128>>>(Qb, Kb, Vb, Cb, S);

    split3<<<gA, 256>>>(Cb, As, nA, 0);
    split3<<<gW, 256>>>(Wo, Ws, nW, 1);
    gemm_mma<<<gG, 256, GSMEM>>>(As, Ws, bo, (float*)d_out);
}

// round 7
// speedup vs baseline: 1.2358x; 1.0442x over previous
#include <cuda_runtime.h>
#include <cuda_bf16.h>
#include <stdint.h>

#define D 1024
#define HEADS 16
#define DKH 64
#define KP 3072            // split-K' = 3 x 1024
#define LDAB 40            // smem row stride in bf16 (80B, 16B-aligned, conflict-free)
#define NSTAGE 3
#define STAGE_BYTES 20480  // A(128x40x2) + B(128x40x2)
#define GSMEM (NSTAGE * STAGE_BYTES)

// ---------------- scratch (allocation-free rule) ----------------
__device__ __align__(16) float g_Q[2 * 2048 * 1024];
__device__ __align__(16) float g_K[2 * 2048 * 1024];
__device__ __align__(16) float g_V[2 * 2048 * 1024];
__device__ __align__(16) float g_C[2 * 2048 * 1024];
// per-GEMM operand buffers (no reuse hazards; enables launch reordering)
__device__ __align__(16) __nv_bfloat16 g_Aq[4096 * KP];
__device__ __align__(16) __nv_bfloat16 g_Ak[4096 * KP];
__device__ __align__(16) __nv_bfloat16 g_Av[4096 * KP];
__device__ __align__(16) __nv_bfloat16 g_Ac[4096 * KP];
__device__ __align__(16) __nv_bfloat16 g_Wq2[1024 * KP];
__device__ __align__(16) __nv_bfloat16 g_Wk2[1024 * KP];
__device__ __align__(16) __nv_bfloat16 g_Wv2[1024 * KP];
__device__ __align__(16) __nv_bfloat16 g_Wo2[1024 * KP];

// ---------------- PTX helpers (plain sm_103 ISA only) ----------------
__device__ __forceinline__ uint32_t smem_u32(const void* p) {
    uint32_t a;
    asm("{ .reg .u64 t; cvta.to.shared.u64 t, %1; cvt.u32.u64 %0, t; }" : "=r"(a) : "l"(p));
    return a;
}
__device__ __forceinline__ void cp16(uint32_t dst, const void* src) {
    asm volatile("cp.async.cg.shared.global [%0], [%1], 16;\n" :: "r"(dst), "l"(src) : "memory");
}
#define CP_COMMIT() asm volatile("cp.async.commit_group;\n" ::: "memory")
#define CP_WAIT(n) asm volatile("cp.async.wait_group %0;\n" :: "n"(n) : "memory")

__device__ __forceinline__ void ldsm_x4(uint32_t& r0, uint32_t& r1, uint32_t& r2, uint32_t& r3, uint32_t addr) {
    asm volatile("ldmatrix.sync.aligned.m8n8.x4.shared.b16 {%0,%1,%2,%3}, [%4];"
                 : "=r"(r0), "=r"(r1), "=r"(r2), "=r"(r3) : "r"(addr));
}
__device__ __forceinline__ void mma_bf16(float* c, uint32_t a0, uint32_t a1, uint32_t a2, uint32_t a3,
                                         uint32_t b0, uint32_t b1) {
    asm volatile(
        "mma.sync.aligned.m16n8k16.row.col.f32.bf16.bf16.f32 "
        "{%0,%1,%2,%3}, {%4,%5,%6,%7}, {%8,%9}, {%0,%1,%2,%3};"
        : "+f"(c[0]), "+f"(c[1]), "+f"(c[2]), "+f"(c[3])
        : "r"(a0), "r"(a1), "r"(a2), "r"(a3), "r"(b0), "r"(b1));
}

// ---------------- fp32 -> bf16 hi/lo 3-segment split ----------------
// mode 0 (activations): [hi | hi | lo]   mode 1 (weights): [hi | lo | hi]
// => sum over K'=3072 yields Ahi*Bhi + Ahi*Blo + Alo*Bhi
union B4 { __nv_bfloat162 h2[2]; uint2 u; };

__global__ __launch_bounds__(256) void split3(const float* __restrict__ x,
                                              __nv_bfloat16* __restrict__ out,
                                              int n, int mode) {
    int i = (blockIdx.x * 256 + threadIdx.x) * 4;
    if (i >= n) return;
    float4 v = *(const float4*)(x + i);
    __nv_bfloat16 h0 = __float2bfloat16(v.x), h1 = __float2bfloat16(v.y);
    __nv_bfloat16 h2 = __float2bfloat16(v.z), h3 = __float2bfloat16(v.w);
    __nv_bfloat16 l0 = __float2bfloat16(v.x - __bfloat162float(h0));
    __nv_bfloat16 l1 = __float2bfloat16(v.y - __bfloat162float(h1));
    __nv_bfloat16 l2 = __float2bfloat16(v.z - __bfloat162float(h2));
    __nv_bfloat16 l3 = __float2bfloat16(v.w - __bfloat162float(h3));
    B4 hv, lv;
    hv.h2[0] = __nv_bfloat162(h0, h1); hv.h2[1] = __nv_bfloat162(h2, h3);
    lv.h2[0] = __nv_bfloat162(l0, l1); lv.h2[1] = __nv_bfloat162(l2, l3);
    int row = i >> 10, col = i & 1023;
    size_t base = (size_t)row * KP + col;
    *(uint2*)(out + base) = hv.u;
    if (mode == 0) {
        *(uint2*)(out + base + 1024) = hv.u;
        *(uint2*)(out + base + 2048) = lv.u;
    } else {
        *(uint2*)(out + base + 1024) = lv.u;
        *(uint2*)(out + base + 2048) = hv.u;
    }
}

// ---------------- bf16 mma.sync GEMM: C[M,1024] = A'[M,3072] @ W'[1024,3072]^T (+bias)
// 128x128 CTA tile, BK=32, 256 threads, 3-stage cp.async pipeline, 2 CTAs/SM,
// register double-buffered ldmatrix fragments (software pipelined ldsm/mma).
struct Frags {
    uint32_t a[2][4];
    uint32_t b[8][2];
};

__device__ __forceinline__ void load_stage(uint32_t sm, const __nv_bfloat16* A,
                                           const __nv_bfloat16* B, int bm, int bn,
                                           int it, int tid) {
    size_t kof = (size_t)it * 32;
#pragma unroll
    for (int i = 0; i < 2; i++) {
        int c = tid + 256 * i;
        int r = c >> 2, kc = (c & 3) * 8;
        cp16(sm + (r * LDAB + kc) * 2, A + (size_t)(bm + r) * KP + kof + kc);
    }
#pragma unroll
    for (int i = 0; i < 2; i++) {
        int c = tid + 256 * i;
        int r = c >> 2, kc = (c & 3) * 8;
        cp16(sm + 10240 + (r * LDAB + kc) * 2, B + (size_t)(bn + r) * KP + kof + kc);
    }
}

__global__ __launch_bounds__(256, 2) void gemm_mma(
    const __nv_bfloat16* __restrict__ A, const __nv_bfloat16* __restrict__ W,
    const float* __restrict__ bias, float* __restrict__ C) {
    extern __shared__ char smem[];
    const uint32_t sb = smem_u32(smem);
    const int tid = threadIdx.x;
    const int wid = tid >> 5;
    const int l = tid & 31;
    const int warp_m = wid >> 1;   // 0..3
    const int warp_n = wid & 1;    // 0..1
    const int bm = blockIdx.y * 128;
    const int bn = blockIdx.x * 128;
    const int NIT = KP / 32;       // 96

    float acc[2][8][4];
#pragma unroll
    for (int mi = 0; mi < 2; mi++)
#pragma unroll
        for (int ni = 0; ni < 8; ni++)
#pragma unroll
            for (int r = 0; r < 4; r++) acc[mi][ni][r] = 0.0f;

    // ldmatrix lane addressing (b16 element offsets)
    const int a_row = warp_m * 32 + (l & 15);
    const int a_ko = (l >> 4) << 3;
    const int b_row = warp_n * 64 + ((l >> 4) << 3) + (l & 7);
    const int b_ko = ((l >> 3) & 1) << 3;

    auto ldsm_frags = [&](Frags& f, uint32_t stage, int kcol) {
#pragma unroll
        for (int mi = 0; mi < 2; mi++)
            ldsm_x4(f.a[mi][0], f.a[mi][1], f.a[mi][2], f.a[mi][3],
                    stage + ((a_row + mi * 16) * LDAB + kcol + a_ko) * 2);
#pragma unroll
        for (int p = 0; p < 4; p++) {
            uint32_t r0, r1, r2, r3;
            ldsm_x4(r0, r1, r2, r3,
                    stage + 10240 + ((b_row + p * 16) * LDAB + kcol + b_ko) * 2);
            f.b[2 * p][0] = r0; f.b[2 * p][1] = r1;
            f.b[2 * p + 1][0] = r2; f.b[2 * p + 1][1] = r3;
        }
    };
    auto mma_all = [&](const Frags& f) {
#pragma unroll
        for (int mi = 0; mi < 2; mi++)
#pragma unroll
            for (int ni = 0; ni < 8; ni++)
                mma_bf16(acc[mi][ni], f.a[mi][0], f.a[mi][1], f.a[mi][2], f.a[mi][3],
                         f.b[ni][0], f.b[ni][1]);
    };

    // prologue: issue stages 0,1
#pragma unroll
    for (int s = 0; s < NSTAGE - 1; s++) {
        load_stage(sb + s * STAGE_BYTES, A, W, bm, bn, s, tid);
        CP_COMMIT();
    }
    CP_WAIT(1);
    __syncthreads();

    Frags cur, nxt;
    ldsm_frags(cur, sb, 0);  // (it=0, kk=0)

    for (int it = 0; it < NIT; it++) {
        const uint32_t sCur = sb + (it % NSTAGE) * STAGE_BYTES;
        // issue gmem loads for stage it+2 (overwrites stage it-1; all warps past
        // last iteration's barrier => done reading it)
        if (it + 2 < NIT)
            load_stage(sb + ((it + 2) % NSTAGE) * STAGE_BYTES, A, W, bm, bn, it + 2, tid);
        CP_COMMIT();

        ldsm_frags(nxt, sCur, 16);  // (it, kk=1) — hidden under mma below
        mma_all(cur);               // kk=0

        if (it + 1 < NIT) {
            CP_WAIT(1);             // stage it+1 landed (group it+2 still pending)
            __syncthreads();        // all warps done reading stage it
            ldsm_frags(cur, sb + ((it + 1) % NSTAGE) * STAGE_BYTES, 0);  // (it+1, kk=0)
        }
        mma_all(nxt);               // kk=1
    }

    // epilogue: per-thread fragment writeback (float2 stores)
    const int tr = l >> 2;         // 0..7
    const int tc = (l & 3) * 2;    // 0,2,4,6
#pragma unroll
    for (int mi = 0; mi < 2; mi++) {
#pragma unroll
        for (int ni = 0; ni < 8; ni++) {
            int row0 = bm + warp_m * 32 + mi * 16 + tr;
            int col = bn + warp_n * 64 + ni * 8 + tc;
            float2 v0 = make_float2(acc[mi][ni][0], acc[mi][ni][1]);
            float2 v1 = make_float2(acc[mi][ni][2], acc[mi][ni][3]);
            if (bias) {
                float2 bv = *(const float2*)(bias + col);
                v0.x += bv.x; v0.y += bv.y;
                v1.x += bv.x; v1.y += bv.y;
            }
            *(float2*)(C + (size_t)row0 * 1024 + col) = v0;
            *(float2*)(C + (size_t)(row0 + 8) * 1024 + col) = v1;
        }
    }
}

// ---------------- flash attention (unchanged, fp32 f32x2 path) ----------------
__device__ __forceinline__ unsigned long long fma2(unsigned long long a, unsigned long long b, unsigned long long c) {
    unsigned long long d;
    asm("fma.rn.f32x2 %0, %1, %2, %3;" : "=l"(d) : "l"(a), "l"(b), "l"(c));
    return d;
}
__device__ __forceinline__ unsigned long long mul2(unsigned long long a, unsigned long long b) {
    unsigned long long d;
    asm("mul.rn.f32x2 %0, %1, %2;" : "=l"(d) : "l"(a), "l"(b));
    return d;
}
__device__ __forceinline__ unsigned long long add2(unsigned long long a, unsigned long long b) {
    unsigned long long d;
    asm("add.rn.f32x2 %0, %1, %2;" : "=l"(d) : "l"(a), "l"(b));
    return d;
}
__device__ __forceinline__ unsigned long long rep2(float x) {
    unsigned long long r;
    asm("mov.b64 %0, {%1, %1};" : "=l"(r) : "f"(x));
    return r;
}
__device__ __forceinline__ float2 unpack2(unsigned long long v) {
    float2 f;
    asm("mov.b64 {%0, %1}, %2;" : "=f"(f.x), "=f"(f.y) : "l"(v));
    return f;
}
union F4U {
    float4 f;
    unsigned long long u[2];
};

__global__ __launch_bounds__(128) void attn_kernel(
    const float* __restrict__ Qm, const float* __restrict__ Km,
    const float* __restrict__ Vm, float* __restrict__ O, int S) {
    __shared__ float Kt[64][64];
    __shared__ float Vt[64][64];

    const int tid = threadIdx.x;
    const int h = blockIdx.y;
    const int b = blockIdx.z;
    const int q = blockIdx.x * 128 + tid;
    const size_t baseQ = ((size_t)b * S + q) * D + (size_t)h * DKH;

    unsigned long long qp[32];
    {
        const float4* qs = (const float4*)(Qm + baseQ);
#pragma unroll
        for (int i = 0; i < 16; i++) {
            F4U t;
            t.f = qs[i];
            t.f.x *= 0.125f; t.f.y *= 0.125f; t.f.z *= 0.125f; t.f.w *= 0.125f;
            qp[2 * i] = t.u[0];
            qp[2 * i + 1] = t.u[1];
        }
    }

    unsigned long long accp[32];
#pragma unroll
    for (int i = 0; i < 32; i++) accp[i] = 0ull;
    float m = -1e30f, lsum = 0.0f;

    const int lrow0 = tid >> 4;
    const int lcol = (tid & 15) * 4;

    for (int kt = 0; kt < S; kt += 64) {
#pragma unroll
        for (int p = 0; p < 8; p++) {
            int r = p * 8 + lrow0;
            size_t g = ((size_t)b * S + kt + r) * D + (size_t)h * DKH + lcol;
            *(float4*)&Kt[r][lcol] = *(const float4*)(Km + g);
            *(float4*)&Vt[r][lcol] = *(const float4*)(Vm + g);
        }
        __syncthreads();

        for (int j = 0; j < 64; j++) {
            const F4U* kr = (const F4U*)&Kt[j][0];
            unsigned long long s0 = 0ull, s1 = 0ull, s2 = 0ull, s3 = 0ull;
#pragma unroll
            for (int i = 0; i < 4; i++) {
                F4U k0 = kr[4 * i + 0];
                F4U k1 = kr[4 * i + 1];
                F4U k2 = kr[4 * i + 2];
                F4U k3 = kr[4 * i + 3];
                s0 = fma2(qp[8 * i + 0], k0.u[0], s0);
                s0 = fma2(qp[8 * i + 1], k0.u[1], s0);
                s1 = fma2(qp[8 * i + 2], k1.u[0], s1);
                s1 = fma2(qp[8 * i + 3], k1.u[1], s1);
                s2 = fma2(qp[8 * i + 4], k2.u[0], s2);
                s2 = fma2(qp[8 * i + 5], k2.u[1], s2);
                s3 = fma2(qp[8 * i + 6], k3.u[0], s3);
                s3 = fma2(qp[8 * i + 7], k3.u[1], s3);
            }
            unsigned long long st = add2(add2(s0, s1), add2(s2, s3));
            float2 sf = unpack2(st);
            float s = sf.x + sf.y;

            float mn = fmaxf(m, s);
            float p = __expf(s - mn);
            float corr = __expf(m - mn);
            lsum = lsum * corr + p;
            if (__any_sync(0xffffffffu, mn > m)) {
                unsigned long long c2 = rep2(corr);
#pragma unroll
                for (int i = 0; i < 32; i++) accp[i] = mul2(accp[i], c2);
            }
            m = mn;

            unsigned long long p2 = rep2(p);
            const F4U* vr = (const F4U*)&Vt[j][0];
#pragma unroll
            for (int i = 0; i < 16; i++) {
                F4U v = vr[i];
                accp[2 * i] = fma2(p2, v.u[0], accp[2 * i]);
                accp[2 * i + 1] = fma2(p2, v.u[1], accp[2 * i + 1]);
            }
        }
        __syncthreads();
    }

    float inv = 1.0f / lsum;
    unsigned long long inv2 = rep2(inv);
    float4* Op = (float4*)(O + baseQ);
#pragma unroll
    for (int i = 0; i < 16; i++) {
        F4U o;
        o.u[0] = mul2(accp[2 * i], inv2);
        o.u[1] = mul2(accp[2 * i + 1], inv2);
        Op[i] = o.f;
    }
}

// ---------------- launch ----------------
extern "C" void kernel_launch(void* const* d_in, const int* in_sizes, int n_in,
                              void* d_out, int out_size) {
    const float* key = (const float*)d_in[0];
    const float* query = (const float*)d_in[1];
    const float* value = (const float*)d_in[2];
    const float* Wq = (const float*)d_in[3];
    const float* Wk = (const float*)d_in[4];
    const float* Wv = (const float*)d_in[5];
    const float* Wo = (const float*)d_in[6];
    const float* bo = (const float*)d_in[7];

    const int B = 2;
    const int S = in_sizes[0] / (B * D);  // 2048
    const int M = B * S;                  // 4096
    const int nA = M * D;
    const int nW = D * D;

    float *Qb, *Kb, *Vb, *Cb;
    __nv_bfloat16 *Aq, *Ak, *Av, *Ac, *Wq2, *Wk2, *Wv2, *Wo2;
    cudaGetSymbolAddress((void**)&Qb, g_Q);
    cudaGetSymbolAddress((void**)&Kb, g_K);
    cudaGetSymbolAddress((void**)&Vb, g_V);
    cudaGetSymbolAddress((void**)&Cb, g_C);
    cudaGetSymbolAddress((void**)&Aq, g_Aq);
    cudaGetSymbolAddress((void**)&Ak, g_Ak);
    cudaGetSymbolAddress((void**)&Av, g_Av);
    cudaGetSymbolAddress((void**)&Ac, g_Ac);
    cudaGetSymbolAddress((void**)&Wq2, g_Wq2);
    cudaGetSymbolAddress((void**)&Wk2, g_Wk2);
    cudaGetSymbolAddress((void**)&Wv2, g_Wv2);
    cudaGetSymbolAddress((void**)&Wo2, g_Wo2);

    cudaFuncSetAttribute(gemm_mma, cudaFuncAttributeMaxDynamicSharedMemorySize, GSMEM);

    dim3 gG(D / 128, M / 128);  // (8, 32)
    const int gA = nA / 1024, gW = nW / 1024;

    // order chosen so launches #5 and #6 (either 0- or 1-based) are gemm_mma,
    // making the ncu -s 5 -c 1 capture land on the GEMM.
    split3<<<gA, 256>>>(query, Aq, nA, 0);   // 1
    split3<<<gW, 256>>>(Wq, Wq2, nW, 1);     // 2
    split3<<<gA, 256>>>(key, Ak, nA, 0);     // 3
    split3<<<gW, 256>>>(Wk, Wk2, nW, 1);     // 4
    gemm_mma<<<gG, 256, GSMEM>>>(Aq, Wq2, nullptr, Qb);  // 5
    gemm_mma<<<gG, 256, GSMEM>>>(Ak, Wk2, nullptr, Kb);  // 6
    split3<<<gA, 256>>>(value, Av, nA, 0);   // 7
    split3<<<gW, 256>>>(Wv, Wv2, nW, 1);     // 8
    gemm_mma<<<gG, 256, GSMEM>>>(Av, Wv2, nullptr, Vb);  // 9

    dim3 gAt(S / 128, HEADS, B);
    attn_kernel<<<gAt, 128>>>(Qb, Kb, Vb, Cb, S);        // 10

    split3<<<gA, 256>>>(Cb, Ac, nA, 0);      // 11
    split3<<<gW, 256>>>(Wo, Wo2, nW, 1);     // 12
    gemm_mma<<<gG, 256, GSMEM>>>(Ac, Wo2, bo, (float*)d_out);  // 13
}

// round 9
// speedup vs baseline: 1.2464x; 1.0086x over previous
#include <cuda_runtime.h>
#include <cuda_bf16.h>
#include <stdint.h>

#define D 1024
#define HEADS 16
#define DKH 64
#define KP 3072            // split-K' = 3 x 1024
#define LDAB 40            // smem row stride in bf16 (80B, 16B-aligned, conflict-free)
#define NSTAGE 3
#define STAGE_BYTES 20480  // A(128x40x2) + B(128x40x2)
#define GSMEM (NSTAGE * STAGE_BYTES)

// ---------------- scratch (allocation-free rule) ----------------
__device__ __align__(16) float g_Q[2 * 2048 * 1024];
__device__ __align__(16) float g_K[2 * 2048 * 1024];
__device__ __align__(16) float g_V[2 * 2048 * 1024];
__device__ __align__(16) float g_C[2 * 2048 * 1024];
// per-GEMM operand buffers
__device__ __align__(16) __nv_bfloat16 g_Aq[4096 * KP];
__device__ __align__(16) __nv_bfloat16 g_Ak[4096 * KP];
__device__ __align__(16) __nv_bfloat16 g_Av[4096 * KP];
__device__ __align__(16) __nv_bfloat16 g_Ac[4096 * KP];
__device__ __align__(16) __nv_bfloat16 g_Wq2[1024 * KP];
__device__ __align__(16) __nv_bfloat16 g_Wk2[1024 * KP];
__device__ __align__(16) __nv_bfloat16 g_Wv2[1024 * KP];
__device__ __align__(16) __nv_bfloat16 g_Wo2[1024 * KP];

// ---------------- PTX helpers (plain sm_103 ISA only) ----------------
__device__ __forceinline__ uint32_t smem_u32(const void* p) {
    uint32_t a;
    asm("{ .reg .u64 t; cvta.to.shared.u64 t, %1; cvt.u32.u64 %0, t; }" : "=r"(a) : "l"(p));
    return a;
}
__device__ __forceinline__ void cp16(uint32_t dst, const void* src) {
    asm volatile("cp.async.cg.shared.global [%0], [%1], 16;\n" :: "r"(dst), "l"(src) : "memory");
}
#define CP_COMMIT() asm volatile("cp.async.commit_group;\n" ::: "memory")
#define CP_WAIT(n) asm volatile("cp.async.wait_group %0;\n" :: "n"(n) : "memory")

__device__ __forceinline__ void ldsm_x4(uint32_t& r0, uint32_t& r1, uint32_t& r2, uint32_t& r3, uint32_t addr) {
    asm volatile("ldmatrix.sync.aligned.m8n8.x4.shared.b16 {%0,%1,%2,%3}, [%4];"
                 : "=r"(r0), "=r"(r1), "=r"(r2), "=r"(r3) : "r"(addr));
}
__device__ __forceinline__ void mma_bf16(float* c, uint32_t a0, uint32_t a1, uint32_t a2, uint32_t a3,
                                         uint32_t b0, uint32_t b1) {
    asm volatile(
        "mma.sync.aligned.m16n8k16.row.col.f32.bf16.bf16.f32 "
        "{%0,%1,%2,%3}, {%4,%5,%6,%7}, {%8,%9}, {%0,%1,%2,%3};"
        : "+f"(c[0]), "+f"(c[1]), "+f"(c[2]), "+f"(c[3])
        : "r"(a0), "r"(a1), "r"(a2), "r"(a3), "r"(b0), "r"(b1));
}

// ---------------- fp32 -> bf16 hi/lo 3-segment split ----------------
// mode 0 (activations): [hi | hi | lo]   mode 1 (weights): [hi | lo | hi]
// => sum over K'=3072 yields Ahi*Bhi + Ahi*Blo + Alo*Bhi
union B4 { __nv_bfloat162 h2[2]; uint2 u; };

__device__ __forceinline__ void split_one(const float* __restrict__ x,
                                          __nv_bfloat16* __restrict__ out,
                                          int i, int mode) {
    float4 v = *(const float4*)(x + i);
    __nv_bfloat16 h0 = __float2bfloat16(v.x), h1 = __float2bfloat16(v.y);
    __nv_bfloat16 h2 = __float2bfloat16(v.z), h3 = __float2bfloat16(v.w);
    __nv_bfloat16 l0 = __float2bfloat16(v.x - __bfloat162float(h0));
    __nv_bfloat16 l1 = __float2bfloat16(v.y - __bfloat162float(h1));
    __nv_bfloat16 l2 = __float2bfloat16(v.z - __bfloat162float(h2));
    __nv_bfloat16 l3 = __float2bfloat16(v.w - __bfloat162float(h3));
    B4 hv, lv;
    hv.h2[0] = __nv_bfloat162(h0, h1); hv.h2[1] = __nv_bfloat162(h2, h3);
    lv.h2[0] = __nv_bfloat162(l0, l1); lv.h2[1] = __nv_bfloat162(l2, l3);
    int row = i >> 10, col = i & 1023;
    size_t base = (size_t)row * KP + col;
    *(uint2*)(out + base) = hv.u;
    if (mode == 0) {
        *(uint2*)(out + base + 1024) = hv.u;
        *(uint2*)(out + base + 2048) = lv.u;
    } else {
        *(uint2*)(out + base + 1024) = lv.u;
        *(uint2*)(out + base + 2048) = hv.u;
    }
}

// standalone split (for ctx after attention)
__global__ __launch_bounds__(256) void split3(const float* __restrict__ x,
                                              __nv_bfloat16* __restrict__ out,
                                              int n, int mode) {
    int i = (blockIdx.x * 256 + threadIdx.x) * 4;
    if (i >= n) return;
    split_one(x, out, i, mode);
}

// fused split of 3 activations (4096 blocks each) + 4 weights (1024 blocks each)
__global__ __launch_bounds__(256) void split_all(
    const float* __restrict__ q, const float* __restrict__ k, const float* __restrict__ v,
    const float* __restrict__ wq, const float* __restrict__ wk,
    const float* __restrict__ wv, const float* __restrict__ wo,
    __nv_bfloat16* __restrict__ oq, __nv_bfloat16* __restrict__ ok, __nv_bfloat16* __restrict__ ov,
    __nv_bfloat16* __restrict__ owq, __nv_bfloat16* __restrict__ owk,
    __nv_bfloat16* __restrict__ owv, __nv_bfloat16* __restrict__ owo) {
    int bid = blockIdx.x;
    const float* src;
    __nv_bfloat16* dst;
    int mode, lb;
    if (bid < 12288) {
        int t = bid >> 12;          // 0..2
        lb = bid & 4095;
        src = (t == 0) ? q : (t == 1) ? k : v;
        dst = (t == 0) ? oq : (t == 1) ? ok : ov;
        mode = 0;
    } else {
        int t = (bid - 12288) >> 10;  // 0..3
        lb = (bid - 12288) & 1023;
        src = (t == 0) ? wq : (t == 1) ? wk : (t == 2) ? wv : wo;
        dst = (t == 0) ? owq : (t == 1) ? owk : (t == 2) ? owv : owo;
        mode = 1;
    }
    int i = (lb * 256 + threadIdx.x) * 4;
    split_one(src, dst, i, mode);
}

// ---------------- bf16 mma.sync GEMM: C[M,1024] = A'[M,3072] @ W'[1024,3072]^T (+bias)
// 128x128 CTA tile, BK=32, 256 threads, 3-stage cp.async pipeline, 2 CTAs/SM,
// register double-buffered ldmatrix fragments.
struct Frags {
    uint32_t a[2][4];
    uint32_t b[8][2];
};

__device__ __forceinline__ void load_stage(uint32_t sm, const __nv_bfloat16* A,
                                           const __nv_bfloat16* B, int bm, int bn,
                                           int it, int tid) {
    size_t kof = (size_t)it * 32;
#pragma unroll
    for (int i = 0; i < 2; i++) {
        int c = tid + 256 * i;
        int r = c >> 2, kc = (c & 3) * 8;
        cp16(sm + (r * LDAB + kc) * 2, A + (size_t)(bm + r) * KP + kof + kc);
    }
#pragma unroll
    for (int i = 0; i < 2; i++) {
        int c = tid + 256 * i;
        int r = c >> 2, kc = (c & 3) * 8;
        cp16(sm + 10240 + (r * LDAB + kc) * 2, B + (size_t)(bn + r) * KP + kof + kc);
    }
}

__global__ __launch_bounds__(256, 2) void gemm_mma(
    const __nv_bfloat16* __restrict__ A, const __nv_bfloat16* __restrict__ W,
    const float* __restrict__ bias, float* __restrict__ C) {
    extern __shared__ char smem[];
    const uint32_t sb = smem_u32(smem);
    const int tid = threadIdx.x;
    const int wid = tid >> 5;
    const int l = tid & 31;
    const int warp_m = wid >> 1;   // 0..3
    const int warp_n = wid & 1;    // 0..1
    const int bm = blockIdx.y * 128;
    const int bn = blockIdx.x * 128;
    const int NIT = KP / 32;       // 96

    float acc[2][8][4];
#pragma unroll
    for (int mi = 0; mi < 2; mi++)
#pragma unroll
        for (int ni = 0; ni < 8; ni++)
#pragma unroll
            for (int r = 0; r < 4; r++) acc[mi][ni][r] = 0.0f;

    const int a_row = warp_m * 32 + (l & 15);
    const int a_ko = (l >> 4) << 3;
    const int b_row = warp_n * 64 + ((l >> 4) << 3) + (l & 7);
    const int b_ko = ((l >> 3) & 1) << 3;

    auto ldsm_frags = [&](Frags& f, uint32_t stage, int kcol) {
#pragma unroll
        for (int mi = 0; mi < 2; mi++)
            ldsm_x4(f.a[mi][0], f.a[mi][1], f.a[mi][2], f.a[mi][3],
                    stage + ((a_row + mi * 16) * LDAB + kcol + a_ko) * 2);
#pragma unroll
        for (int p = 0; p < 4; p++) {
            uint32_t r0, r1, r2, r3;
            ldsm_x4(r0, r1, r2, r3,
                    stage + 10240 + ((b_row + p * 16) * LDAB + kcol + b_ko) * 2);
            f.b[2 * p][0] = r0; f.b[2 * p][1] = r1;
            f.b[2 * p + 1][0] = r2; f.b[2 * p + 1][1] = r3;
        }
    };
    auto mma_all = [&](const Frags& f) {
#pragma unroll
        for (int mi = 0; mi < 2; mi++)
#pragma unroll
            for (int ni = 0; ni < 8; ni++)
                mma_bf16(acc[mi][ni], f.a[mi][0], f.a[mi][1], f.a[mi][2], f.a[mi][3],
                         f.b[ni][0], f.b[ni][1]);
    };

#pragma unroll
    for (int s = 0; s < NSTAGE - 1; s++) {
        load_stage(sb + s * STAGE_BYTES, A, W, bm, bn, s, tid);
        CP_COMMIT();
    }
    CP_WAIT(1);
    __syncthreads();

    Frags cur, nxt;
    ldsm_frags(cur, sb, 0);

    for (int it = 0; it < NIT; it++) {
        const uint32_t sCur = sb + (it % NSTAGE) * STAGE_BYTES;
        if (it + 2 < NIT)
            load_stage(sb + ((it + 2) % NSTAGE) * STAGE_BYTES, A, W, bm, bn, it + 2, tid);
        CP_COMMIT();

        ldsm_frags(nxt, sCur, 16);
        mma_all(cur);

        if (it + 1 < NIT) {
            CP_WAIT(1);
            __syncthreads();
            ldsm_frags(cur, sb + ((it + 1) % NSTAGE) * STAGE_BYTES, 0);
        }
        mma_all(nxt);
    }

    const int tr = l >> 2;
    const int tc = (l & 3) * 2;
#pragma unroll
    for (int mi = 0; mi < 2; mi++) {
#pragma unroll
        for (int ni = 0; ni < 8; ni++) {
            int row0 = bm + warp_m * 32 + mi * 16 + tr;
            int col = bn + warp_n * 64 + ni * 8 + tc;
            float2 v0 = make_float2(acc[mi][ni][0], acc[mi][ni][1]);
            float2 v1 = make_float2(acc[mi][ni][2], acc[mi][ni][3]);
            if (bias) {
                float2 bv = *(const float2*)(bias + col);
                v0.x += bv.x; v0.y += bv.y;
                v1.x += bv.x; v1.y += bv.y;
            }
            *(float2*)(C + (size_t)row0 * 1024 + col) = v0;
            *(float2*)(C + (size_t)(row0 + 8) * 1024 + col) = v1;
        }
    }
}

// ---------------- flash attention (unchanged, fp32 f32x2 path) ----------------
__device__ __forceinline__ unsigned long long fma2(unsigned long long a, unsigned long long b, unsigned long long c) {
    unsigned long long d;
    asm("fma.rn.f32x2 %0, %1, %2, %3;" : "=l"(d) : "l"(a), "l"(b), "l"(c));
    return d;
}
__device__ __forceinline__ unsigned long long mul2(unsigned long long a, unsigned long long b) {
    unsigned long long d;
    asm("mul.rn.f32x2 %0, %1, %2;" : "=l"(d) : "l"(a), "l"(b));
    return d;
}
__device__ __forceinline__ unsigned long long add2(unsigned long long a, unsigned long long b) {
    unsigned long long d;
    asm("add.rn.f32x2 %0, %1, %2;" : "=l"(d) : "l"(a), "l"(b));
    return d;
}
__device__ __forceinline__ unsigned long long rep2(float x) {
    unsigned long long r;
    asm("mov.b64 %0, {%1, %1};" : "=l"(r) : "f"(x));
    return r;
}
__device__ __forceinline__ float2 unpack2(unsigned long long v) {
    float2 f;
    asm("mov.b64 {%0, %1}, %2;" : "=f"(f.x), "=f"(f.y) : "l"(v));
    return f;
}
union F4U {
    float4 f;
    unsigned long long u[2];
};

__global__ __launch_bounds__(128) void attn_kernel(
    const float* __restrict__ Qm, const float* __restrict__ Km,
    const float* __restrict__ Vm, float* __restrict__ O, int S) {
    __shared__ float Kt[64][64];
    __shared__ float Vt[64][64];

    const int tid = threadIdx.x;
    const int h = blockIdx.y;
    const int b = blockIdx.z;
    const int q = blockIdx.x * 128 + tid;
    const size_t baseQ = ((size_t)b * S + q) * D + (size_t)h * DKH;

    unsigned long long qp[32];
    {
        const float4* qs = (const float4*)(Qm + baseQ);
#pragma unroll
        for (int i = 0; i < 16; i++) {
            F4U t;
            t.f = qs[i];
            t.f.x *= 0.125f; t.f.y *= 0.125f; t.f.z *= 0.125f; t.f.w *= 0.125f;
            qp[2 * i] = t.u[0];
            qp[2 * i + 1] = t.u[1];
        }
    }

    unsigned long long accp[32];
#pragma unroll
    for (int i = 0; i < 32; i++) accp[i] = 0ull;
    float m = -1e30f, lsum = 0.0f;

    const int lrow0 = tid >> 4;
    const int lcol = (tid & 15) * 4;

    for (int kt = 0; kt < S; kt += 64) {
#pragma unroll
        for (int p = 0; p < 8; p++) {
            int r = p * 8 + lrow0;
            size_t g = ((size_t)b * S + kt + r) * D + (size_t)h * DKH + lcol;
            *(float4*)&Kt[r][lcol] = *(const float4*)(Km + g);
            *(float4*)&Vt[r][lcol] = *(const float4*)(Vm + g);
        }
        __syncthreads();

        for (int j = 0; j < 64; j++) {
            const F4U* kr = (const F4U*)&Kt[j][0];
            unsigned long long s0 = 0ull, s1 = 0ull, s2 = 0ull, s3 = 0ull;
#pragma unroll
            for (int i = 0; i < 4; i++) {
                F4U k0 = kr[4 * i + 0];
                F4U k1 = kr[4 * i + 1];
                F4U k2 = kr[4 * i + 2];
                F4U k3 = kr[4 * i + 3];
                s0 = fma2(qp[8 * i + 0], k0.u[0], s0);
                s0 = fma2(qp[8 * i + 1], k0.u[1], s0);
                s1 = fma2(qp[8 * i + 2], k1.u[0], s1);
                s1 = fma2(qp[8 * i + 3], k1.u[1], s1);
                s2 = fma2(qp[8 * i + 4], k2.u[0], s2);
                s2 = fma2(qp[8 * i + 5], k2.u[1], s2);
                s3 = fma2(qp[8 * i + 6], k3.u[0], s3);
                s3 = fma2(qp[8 * i + 7], k3.u[1], s3);
            }
            unsigned long long st = add2(add2(s0, s1), add2(s2, s3));
            float2 sf = unpack2(st);
            float s = sf.x + sf.y;

            float mn = fmaxf(m, s);
            float p = __expf(s - mn);
            float corr = __expf(m - mn);
            lsum = lsum * corr + p;
            if (__any_sync(0xffffffffu, mn > m)) {
                unsigned long long c2 = rep2(corr);
#pragma unroll
                for (int i = 0; i < 32; i++) accp[i] = mul2(accp[i], c2);
            }
            m = mn;

            unsigned long long p2 = rep2(p);
            const F4U* vr = (const F4U*)&Vt[j][0];
#pragma unroll
            for (int i = 0; i < 16; i++) {
                F4U v = vr[i];
                accp[2 * i] = fma2(p2, v.u[0], accp[2 * i]);
                accp[2 * i + 1] = fma2(p2, v.u[1], accp[2 * i + 1]);
            }
        }
        __syncthreads();
    }

    float inv = 1.0f / lsum;
    unsigned long long inv2 = rep2(inv);
    float4* Op = (float4*)(O + baseQ);
#pragma unroll
    for (int i = 0; i < 16; i++) {
        F4U o;
        o.u[0] = mul2(accp[2 * i], inv2);
        o.u[1] = mul2(accp[2 * i + 1], inv2);
        Op[i] = o.f;
    }
}

// ---------------- launch ----------------
extern "C" void kernel_launch(void* const* d_in, const int* in_sizes, int n_in,
                              void* d_out, int out_size) {
    const float* key = (const float*)d_in[0];
    const float* query = (const float*)d_in[1];
    const float* value = (const float*)d_in[2];
    const float* Wq = (const float*)d_in[3];
    const float* Wk = (const float*)d_in[4];
    const float* Wv = (const float*)d_in[5];
    const float* Wo = (const float*)d_in[6];
    const float* bo = (const float*)d_in[7];

    const int B = 2;
    const int S = in_sizes[0] / (B * D);  // 2048
    const int M = B * S;                  // 4096
    const int nA = M * D;

    float *Qb, *Kb, *Vb, *Cb;
    __nv_bfloat16 *Aq, *Ak, *Av, *Ac, *Wq2, *Wk2, *Wv2, *Wo2;
    cudaGetSymbolAddress((void**)&Qb, g_Q);
    cudaGetSymbolAddress((void**)&Kb, g_K);
    cudaGetSymbolAddress((void**)&Vb, g_V);
    cudaGetSymbolAddress((void**)&Cb, g_C);
    cudaGetSymbolAddress((void**)&Aq, g_Aq);
    cudaGetSymbolAddress((void**)&Ak, g_Ak);
    cudaGetSymbolAddress((void**)&Av, g_Av);
    cudaGetSymbolAddress((void**)&Ac, g_Ac);
    cudaGetSymbolAddress((void**)&Wq2, g_Wq2);
    cudaGetSymbolAddress((void**)&Wk2, g_Wk2);
    cudaGetSymbolAddress((void**)&Wv2, g_Wv2);
    cudaGetSymbolAddress((void**)&Wo2, g_Wo2);

    cudaFuncSetAttribute(gemm_mma, cudaFuncAttributeMaxDynamicSharedMemorySize, GSMEM);

    dim3 gG(D / 128, M / 128);  // (8, 32)

    // #1: all input splits fused into one launch (16384 blocks)
    split_all<<<16384, 256>>>(query, key, value, Wq, Wk, Wv, Wo,
                              Aq, Ak, Av, Wq2, Wk2, Wv2, Wo2);
    // #2-#4: projection GEMMs (profiler-friendly consecutive run)
    gemm_mma<<<gG, 256, GSMEM>>>(Aq, Wq2, nullptr, Qb);
    gemm_mma<<<gG, 256, GSMEM>>>(Ak, Wk2, nullptr, Kb);
    gemm_mma<<<gG, 256, GSMEM>>>(Av, Wv2, nullptr, Vb);

    // #5: attention
    dim3 gAt(S / 128, HEADS, B);
    attn_kernel<<<gAt, 128>>>(Qb, Kb, Vb, Cb, S);

    // #6: ctx split, #7: output projection
    split3<<<nA / 1024, 256>>>(Cb, Ac, nA, 0);
    gemm_mma<<<gG, 256, GSMEM>>>(Ac, Wo2, bo, (float*)d_out);
}

// round 11
// speedup vs baseline: 3.0232x; 2.4255x over previous
#include <cuda_runtime.h>
#include <cuda_bf16.h>
#include <stdint.h>

#define D 1024
#define HEADS 16
#define KP 3072            // split-K' = 3 x 1024
#define LDAB 40            // gemm smem row stride in bf16
#define NSTAGE 3
#define STAGE_BYTES 20480
#define GSMEM (NSTAGE * STAGE_BYTES)

#define ATT_T 72                       // attn smem row stride (halves); 144B, 16B-aligned
#define ATT_MAT_B (64 * ATT_T * 2)     // 9216 bytes per 64x64 bf16 matrix
#define ATT_SMEM (2 * ATT_MAT_B + 2 * 4 * ATT_MAT_B)  // Qhi/Qlo + 2 stages x (Khi,Klo,Vhi,Vlo) = 92160

// ---------------- scratch (allocation-free rule) ----------------
__device__ __align__(16) float g_C[2 * 2048 * 1024];
__device__ __align__(16) __nv_bfloat16 g_Qhi[4096 * 1024];
__device__ __align__(16) __nv_bfloat16 g_Qlo[4096 * 1024];
__device__ __align__(16) __nv_bfloat16 g_Khi[4096 * 1024];
__device__ __align__(16) __nv_bfloat16 g_Klo[4096 * 1024];
__device__ __align__(16) __nv_bfloat16 g_Vhi[4096 * 1024];
__device__ __align__(16) __nv_bfloat16 g_Vlo[4096 * 1024];
__device__ __align__(16) __nv_bfloat16 g_Aq[4096 * KP];
__device__ __align__(16) __nv_bfloat16 g_Ak[4096 * KP];
__device__ __align__(16) __nv_bfloat16 g_Av[4096 * KP];
__device__ __align__(16) __nv_bfloat16 g_Ac[4096 * KP];
__device__ __align__(16) __nv_bfloat16 g_Wq2[1024 * KP];
__device__ __align__(16) __nv_bfloat16 g_Wk2[1024 * KP];
__device__ __align__(16) __nv_bfloat16 g_Wv2[1024 * KP];
__device__ __align__(16) __nv_bfloat16 g_Wo2[1024 * KP];

// ---------------- PTX helpers (plain sm_103 ISA only) ----------------
__device__ __forceinline__ uint32_t smem_u32(const void* p) {
    uint32_t a;
    asm("{ .reg .u64 t; cvta.to.shared.u64 t, %1; cvt.u32.u64 %0, t; }" : "=r"(a) : "l"(p));
    return a;
}
__device__ __forceinline__ void cp16(uint32_t dst, const void* src) {
    asm volatile("cp.async.cg.shared.global [%0], [%1], 16;\n" :: "r"(dst), "l"(src) : "memory");
}
#define CP_COMMIT() asm volatile("cp.async.commit_group;\n" ::: "memory")
#define CP_WAIT(n) asm volatile("cp.async.wait_group %0;\n" :: "n"(n) : "memory")

__device__ __forceinline__ void ldsm_x4(uint32_t& r0, uint32_t& r1, uint32_t& r2, uint32_t& r3, uint32_t addr) {
    asm volatile("ldmatrix.sync.aligned.m8n8.x4.shared.b16 {%0,%1,%2,%3}, [%4];"
                 : "=r"(r0), "=r"(r1), "=r"(r2), "=r"(r3) : "r"(addr));
}
__device__ __forceinline__ void ldsm_x4_t(uint32_t& r0, uint32_t& r1, uint32_t& r2, uint32_t& r3, uint32_t addr) {
    asm volatile("ldmatrix.sync.aligned.m8n8.x4.trans.shared.b16 {%0,%1,%2,%3}, [%4];"
                 : "=r"(r0), "=r"(r1), "=r"(r2), "=r"(r3) : "r"(addr));
}
__device__ __forceinline__ void mma_bf16(float* c, uint32_t a0, uint32_t a1, uint32_t a2, uint32_t a3,
                                         uint32_t b0, uint32_t b1) {
    asm volatile(
        "mma.sync.aligned.m16n8k16.row.col.f32.bf16.bf16.f32 "
        "{%0,%1,%2,%3}, {%4,%5,%6,%7}, {%8,%9}, {%0,%1,%2,%3};"
        : "+f"(c[0]), "+f"(c[1]), "+f"(c[2]), "+f"(c[3])
        : "r"(a0), "r"(a1), "r"(a2), "r"(a3), "r"(b0), "r"(b1));
}

// ---------------- fp32 -> bf16 hi/lo 3-segment split ----------------
union B4 { __nv_bfloat162 h2[2]; uint2 u; };

__device__ __forceinline__ void split_one(const float* __restrict__ x,
                                          __nv_bfloat16* __restrict__ out,
                                          int i, int mode) {
    float4 v = *(const float4*)(x + i);
    __nv_bfloat16 h0 = __float2bfloat16(v.x), h1 = __float2bfloat16(v.y);
    __nv_bfloat16 h2 = __float2bfloat16(v.z), h3 = __float2bfloat16(v.w);
    __nv_bfloat16 l0 = __float2bfloat16(v.x - __bfloat162float(h0));
    __nv_bfloat16 l1 = __float2bfloat16(v.y - __bfloat162float(h1));
    __nv_bfloat16 l2 = __float2bfloat16(v.z - __bfloat162float(h2));
    __nv_bfloat16 l3 = __float2bfloat16(v.w - __bfloat162float(h3));
    B4 hv, lv;
    hv.h2[0] = __nv_bfloat162(h0, h1); hv.h2[1] = __nv_bfloat162(h2, h3);
    lv.h2[0] = __nv_bfloat162(l0, l1); lv.h2[1] = __nv_bfloat162(l2, l3);
    int row = i >> 10, col = i & 1023;
    size_t base = (size_t)row * KP + col;
    *(uint2*)(out + base) = hv.u;
    if (mode == 0) {
        *(uint2*)(out + base + 1024) = hv.u;
        *(uint2*)(out + base + 2048) = lv.u;
    } else {
        *(uint2*)(out + base + 1024) = lv.u;
        *(uint2*)(out + base + 2048) = hv.u;
    }
}

__global__ __launch_bounds__(256) void split3(const float* __restrict__ x,
                                              __nv_bfloat16* __restrict__ out,
                                              int n, int mode) {
    int i = (blockIdx.x * 256 + threadIdx.x) * 4;
    if (i >= n) return;
    split_one(x, out, i, mode);
}

__global__ __launch_bounds__(256) void split_all(
    const float* __restrict__ q, const float* __restrict__ k, const float* __restrict__ v,
    const float* __restrict__ wq, const float* __restrict__ wk,
    const float* __restrict__ wv, const float* __restrict__ wo,
    __nv_bfloat16* __restrict__ oq, __nv_bfloat16* __restrict__ ok, __nv_bfloat16* __restrict__ ov,
    __nv_bfloat16* __restrict__ owq, __nv_bfloat16* __restrict__ owk,
    __nv_bfloat16* __restrict__ owv, __nv_bfloat16* __restrict__ owo) {
    int bid = blockIdx.x;
    const float* src;
    __nv_bfloat16* dst;
    int mode, lb;
    if (bid < 12288) {
        int t = bid >> 12;
        lb = bid & 4095;
        src = (t == 0) ? q : (t == 1) ? k : v;
        dst = (t == 0) ? oq : (t == 1) ? ok : ov;
        mode = 0;
    } else {
        int t = (bid - 12288) >> 10;
        lb = (bid - 12288) & 1023;
        src = (t == 0) ? wq : (t == 1) ? wk : (t == 2) ? wv : wo;
        dst = (t == 0) ? owq : (t == 1) ? owk : (t == 2) ? owv : owo;
        mode = 1;
    }
    int i = (lb * 256 + threadIdx.x) * 4;
    split_one(src, dst, i, mode);
}

// ---------------- bf16 mma.sync GEMM ----------------
struct Frags {
    uint32_t a[2][4];
    uint32_t b[8][2];
};

__device__ __forceinline__ void load_stage(uint32_t sm, const __nv_bfloat16* A,
                                           const __nv_bfloat16* B, int bm, int bn,
                                           int it, int tid) {
    size_t kof = (size_t)it * 32;
#pragma unroll
    for (int i = 0; i < 2; i++) {
        int c = tid + 256 * i;
        int r = c >> 2, kc = (c & 3) * 8;
        cp16(sm + (r * LDAB + kc) * 2, A + (size_t)(bm + r) * KP + kof + kc);
    }
#pragma unroll
    for (int i = 0; i < 2; i++) {
        int c = tid + 256 * i;
        int r = c >> 2, kc = (c & 3) * 8;
        cp16(sm + 10240 + (r * LDAB + kc) * 2, B + (size_t)(bn + r) * KP + kof + kc);
    }
}

__global__ __launch_bounds__(256, 2) void gemm_mma(
    const __nv_bfloat16* __restrict__ A, const __nv_bfloat16* __restrict__ W,
    const float* __restrict__ bias, float* __restrict__ C,
    __nv_bfloat16* __restrict__ Chi, __nv_bfloat16* __restrict__ Clo) {
    extern __shared__ char smem[];
    const uint32_t sb = smem_u32(smem);
    const int tid = threadIdx.x;
    const int wid = tid >> 5;
    const int l = tid & 31;
    const int warp_m = wid >> 1;
    const int warp_n = wid & 1;
    const int bm = blockIdx.y * 128;
    const int bn = blockIdx.x * 128;
    const int NIT = KP / 32;

    float acc[2][8][4];
#pragma unroll
    for (int mi = 0; mi < 2; mi++)
#pragma unroll
        for (int ni = 0; ni < 8; ni++)
#pragma unroll
            for (int r = 0; r < 4; r++) acc[mi][ni][r] = 0.0f;

    const int a_row = warp_m * 32 + (l & 15);
    const int a_ko = (l >> 4) << 3;
    const int b_row = warp_n * 64 + ((l >> 4) << 3) + (l & 7);
    const int b_ko = ((l >> 3) & 1) << 3;

    auto ldsm_frags = [&](Frags& f, uint32_t stage, int kcol) {
#pragma unroll
        for (int mi = 0; mi < 2; mi++)
            ldsm_x4(f.a[mi][0], f.a[mi][1], f.a[mi][2], f.a[mi][3],
                    stage + ((a_row + mi * 16) * LDAB + kcol + a_ko) * 2);
#pragma unroll
        for (int p = 0; p < 4; p++) {
            uint32_t r0, r1, r2, r3;
            ldsm_x4(r0, r1, r2, r3,
                    stage + 10240 + ((b_row + p * 16) * LDAB + kcol + b_ko) * 2);
            f.b[2 * p][0] = r0; f.b[2 * p][1] = r1;
            f.b[2 * p + 1][0] = r2; f.b[2 * p + 1][1] = r3;
        }
    };
    auto mma_all = [&](const Frags& f) {
#pragma unroll
        for (int mi = 0; mi < 2; mi++)
#pragma unroll
            for (int ni = 0; ni < 8; ni++)
                mma_bf16(acc[mi][ni], f.a[mi][0], f.a[mi][1], f.a[mi][2], f.a[mi][3],
                         f.b[ni][0], f.b[ni][1]);
    };

#pragma unroll
    for (int s = 0; s < NSTAGE - 1; s++) {
        load_stage(sb + s * STAGE_BYTES, A, W, bm, bn, s, tid);
        CP_COMMIT();
    }
    CP_WAIT(1);
    __syncthreads();

    Frags cur, nxt;
    ldsm_frags(cur, sb, 0);

    for (int it = 0; it < NIT; it++) {
        const uint32_t sCur = sb + (it % NSTAGE) * STAGE_BYTES;
        if (it + 2 < NIT)
            load_stage(sb + ((it + 2) % NSTAGE) * STAGE_BYTES, A, W, bm, bn, it + 2, tid);
        CP_COMMIT();

        ldsm_frags(nxt, sCur, 16);
        mma_all(cur);

        if (it + 1 < NIT) {
            CP_WAIT(1);
            __syncthreads();
            ldsm_frags(cur, sb + ((it + 1) % NSTAGE) * STAGE_BYTES, 0);
        }
        mma_all(nxt);
    }

    const int tr = l >> 2;
    const int tc = (l & 3) * 2;
#pragma unroll
    for (int mi = 0; mi < 2; mi++) {
#pragma unroll
        for (int ni = 0; ni < 8; ni++) {
            int row0 = bm + warp_m * 32 + mi * 16 + tr;
            int col = bn + warp_n * 64 + ni * 8 + tc;
            float2 v0 = make_float2(acc[mi][ni][0], acc[mi][ni][1]);
            float2 v1 = make_float2(acc[mi][ni][2], acc[mi][ni][3]);
            if (bias) {
                float2 bv = *(const float2*)(bias + col);
                v0.x += bv.x; v0.y += bv.y;
                v1.x += bv.x; v1.y += bv.y;
            }
            if (C) {
                *(float2*)(C + (size_t)row0 * 1024 + col) = v0;
                *(float2*)(C + (size_t)(row0 + 8) * 1024 + col) = v1;
            }
            if (Chi) {
                __nv_bfloat16 h0 = __float2bfloat16(v0.x), h1 = __float2bfloat16(v0.y);
                __nv_bfloat16 h2 = __float2bfloat16(v1.x), h3 = __float2bfloat16(v1.y);
                __nv_bfloat162 hp0(h0, h1), hp1(h2, h3);
                __nv_bfloat162 lp0(__float2bfloat16(v0.x - __bfloat162float(h0)),
                                   __float2bfloat16(v0.y - __bfloat162float(h1)));
                __nv_bfloat162 lp1(__float2bfloat16(v1.x - __bfloat162float(h2)),
                                   __float2bfloat16(v1.y - __bfloat162float(h3)));
                *(uint32_t*)(Chi + (size_t)row0 * 1024 + col) = *(uint32_t*)&hp0;
                *(uint32_t*)(Chi + (size_t)(row0 + 8) * 1024 + col) = *(uint32_t*)&hp1;
                *(uint32_t*)(Clo + (size_t)row0 * 1024 + col) = *(uint32_t*)&lp0;
                *(uint32_t*)(Clo + (size_t)(row0 + 8) * 1024 + col) = *(uint32_t*)&lp1;
            }
        }
    }
}

// ---------------- tensor-core flash attention ----------------
// CTA: 64 q-rows x one (b,h); 4 warps, warp = m16. Keys streamed 64/tile, 2-stage cp.async.
// QK^T = Qhi*Khi + Qhi*Klo + Qlo*Khi; PV = Phi*Vhi + Phi*Vlo + Plo*Vhi (errors ~2^-16).
__global__ __launch_bounds__(128) void attn_tc(
    const __nv_bfloat16* __restrict__ Qhi, const __nv_bfloat16* __restrict__ Qlo,
    const __nv_bfloat16* __restrict__ Khi, const __nv_bfloat16* __restrict__ Klo,
    const __nv_bfloat16* __restrict__ Vhi, const __nv_bfloat16* __restrict__ Vlo,
    float* __restrict__ ctx, int S) {
    extern __shared__ char smem[];
    const uint32_t sb = smem_u32(smem);
    const int tid = threadIdx.x;
    const int w = tid >> 5;
    const int l = tid & 31;
    const int tr = l >> 2;
    const int tc = l & 3;
    const int qt = blockIdx.x, h = blockIdx.y, b = blockIdx.z;
    const int NT = S / 64;

    const uint32_t oQhi = sb;
    const uint32_t oQlo = sb + ATT_MAT_B;
    const uint32_t oSt = sb + 2 * ATT_MAT_B;   // stage s at oSt + s*4*ATT_MAT_B

    const size_t gq = ((size_t)(b * S + qt * 64)) * D + (size_t)h * 64;

    // Q: 2 matrices x 64 rows x 8 16B-chunks = 1024 chunks, 8 iters of 128 threads
#pragma unroll
    for (int i = 0; i < 8; i++) {
        int c = tid + 128 * i;
        int mat = c >> 9, r = (c >> 3) & 63, cc = c & 7;
        const __nv_bfloat16* src = mat ? Qlo : Qhi;
        cp16((mat ? oQlo : oQhi) + (r * ATT_T + cc * 8) * 2, src + gq + (size_t)r * D + cc * 8);
    }
    // KV: 4 matrices x 512 chunks = 2048 chunks, 16 iters of 128 threads
    auto load_kv = [&](int stage, int kt) {
        size_t gk = ((size_t)(b * S + kt * 64)) * D + (size_t)h * 64;
        const __nv_bfloat16* mats[4] = {Khi, Klo, Vhi, Vlo};
#pragma unroll
        for (int i = 0; i < 16; i++) {
            int c = tid + 128 * i;
            int mat = c >> 9, r = (c >> 3) & 63, cc = c & 7;
            cp16(oSt + stage * (4 * ATT_MAT_B) + mat * ATT_MAT_B + (r * ATT_T + cc * 8) * 2,
                 mats[mat] + gk + (size_t)r * D + cc * 8);
        }
    };
    load_kv(0, 0);
    CP_COMMIT();
    load_kv(1, 1);
    CP_COMMIT();
    CP_WAIT(1);
    __syncthreads();

    // Q fragments (A operand, m16 x k64, hi and lo)
    uint32_t qh[4][4], ql[4][4];
    {
        const int arow = w * 16 + (l & 15);
        const int ako = (l >> 4) << 3;
#pragma unroll
        for (int kk = 0; kk < 4; kk++) {
            ldsm_x4(qh[kk][0], qh[kk][1], qh[kk][2], qh[kk][3],
                    oQhi + (arow * ATT_T + kk * 16 + ako) * 2);
            ldsm_x4(ql[kk][0], ql[kk][1], ql[kk][2], ql[kk][3],
                    oQlo + (arow * ATT_T + kk * 16 + ako) * 2);
        }
    }

    float oacc[8][4];
#pragma unroll
    for (int ni = 0; ni < 8; ni++)
#pragma unroll
        for (int j = 0; j < 4; j++) oacc[ni][j] = 0.0f;
    float m0 = -1e30f, m1 = -1e30f, sl0 = 0.0f, sl1 = 0.0f;

    const int brow = ((l >> 4) << 3) + (l & 7);         // K b-frag row pattern
    const int bko = ((l >> 3) & 1) << 3;
    const int vrow = (l & 7) + (((l >> 3) & 1) << 3);   // V trans-ldsm row pattern
    const int vcolw = (l >> 4);                          // 0/1: which n8 of the pair

    for (int kt = 0; kt < NT; kt++) {
        const uint32_t KBh = oSt + (kt & 1) * (4 * ATT_MAT_B);
        const uint32_t KBl = KBh + ATT_MAT_B;
        const uint32_t VBh = KBh + 2 * ATT_MAT_B;
        const uint32_t VBl = KBh + 3 * ATT_MAT_B;

        // ---- scores: m16 x n64, 3-term ----
        float sacc[8][4];
#pragma unroll
        for (int ni = 0; ni < 8; ni++)
#pragma unroll
            for (int j = 0; j < 4; j++) sacc[ni][j] = 0.0f;

#pragma unroll
        for (int kk = 0; kk < 4; kk++) {
            uint32_t bh[8][2];
#pragma unroll
            for (int np = 0; np < 4; np++) {
                uint32_t r0, r1, r2, r3;
                ldsm_x4(r0, r1, r2, r3, KBh + ((np * 16 + brow) * ATT_T + kk * 16 + bko) * 2);
                bh[2 * np][0] = r0; bh[2 * np][1] = r1;
                bh[2 * np + 1][0] = r2; bh[2 * np + 1][1] = r3;
            }
#pragma unroll
            for (int ni = 0; ni < 8; ni++)
                mma_bf16(sacc[ni], qh[kk][0], qh[kk][1], qh[kk][2], qh[kk][3], bh[ni][0], bh[ni][1]);
#pragma unroll
            for (int ni = 0; ni < 8; ni++)
                mma_bf16(sacc[ni], ql[kk][0], ql[kk][1], ql[kk][2], ql[kk][3], bh[ni][0], bh[ni][1]);
            uint32_t bl[8][2];
#pragma unroll
            for (int np = 0; np < 4; np++) {
                uint32_t r0, r1, r2, r3;
                ldsm_x4(r0, r1, r2, r3, KBl + ((np * 16 + brow) * ATT_T + kk * 16 + bko) * 2);
                bl[2 * np][0] = r0; bl[2 * np][1] = r1;
                bl[2 * np + 1][0] = r2; bl[2 * np + 1][1] = r3;
            }
#pragma unroll
            for (int ni = 0; ni < 8; ni++)
                mma_bf16(sacc[ni], qh[kk][0], qh[kk][1], qh[kk][2], qh[kk][3], bl[ni][0], bl[ni][1]);
        }

        // ---- online softmax (scale 1/8) ----
        float mx0 = -1e30f, mx1 = -1e30f;
#pragma unroll
        for (int ni = 0; ni < 8; ni++) {
            sacc[ni][0] *= 0.125f; sacc[ni][1] *= 0.125f;
            sacc[ni][2] *= 0.125f; sacc[ni][3] *= 0.125f;
            mx0 = fmaxf(mx0, fmaxf(sacc[ni][0], sacc[ni][1]));
            mx1 = fmaxf(mx1, fmaxf(sacc[ni][2], sacc[ni][3]));
        }
        mx0 = fmaxf(mx0, __shfl_xor_sync(0xffffffffu, mx0, 1));
        mx0 = fmaxf(mx0, __shfl_xor_sync(0xffffffffu, mx0, 2));
        mx1 = fmaxf(mx1, __shfl_xor_sync(0xffffffffu, mx1, 1));
        mx1 = fmaxf(mx1, __shfl_xor_sync(0xffffffffu, mx1, 2));
        float mn0 = fmaxf(m0, mx0), mn1 = fmaxf(m1, mx1);
        float c0 = __expf(m0 - mn0), c1 = __expf(m1 - mn1);
        float rs0 = 0.0f, rs1 = 0.0f;
#pragma unroll
        for (int ni = 0; ni < 8; ni++) {
            sacc[ni][0] = __expf(sacc[ni][0] - mn0);
            sacc[ni][1] = __expf(sacc[ni][1] - mn0);
            sacc[ni][2] = __expf(sacc[ni][2] - mn1);
            sacc[ni][3] = __expf(sacc[ni][3] - mn1);
            rs0 += sacc[ni][0] + sacc[ni][1];
            rs1 += sacc[ni][2] + sacc[ni][3];
        }
        rs0 += __shfl_xor_sync(0xffffffffu, rs0, 1);
        rs0 += __shfl_xor_sync(0xffffffffu, rs0, 2);
        rs1 += __shfl_xor_sync(0xffffffffu, rs1, 1);
        rs1 += __shfl_xor_sync(0xffffffffu, rs1, 2);
        sl0 = sl0 * c0 + rs0;
        sl1 = sl1 * c1 + rs1;
        m0 = mn0; m1 = mn1;
#pragma unroll
        for (int ni = 0; ni < 8; ni++) {
            oacc[ni][0] *= c0; oacc[ni][1] *= c0;
            oacc[ni][2] *= c1; oacc[ni][3] *= c1;
        }

        // ---- P fragments (A operand m16 x k64), bf16 hi/lo split ----
        uint32_t ph[4][4], pl[4][4];
#pragma unroll
        for (int kk = 0; kk < 4; kk++) {
#pragma unroll
            for (int hv = 0; hv < 2; hv++) {
#pragma unroll
                for (int half = 0; half < 2; half++) {
                    float x = sacc[2 * kk + half][2 * hv + 0];
                    float y = sacc[2 * kk + half][2 * hv + 1];
                    __nv_bfloat16 hx = __float2bfloat16(x), hy = __float2bfloat16(y);
                    __nv_bfloat162 hp(hx, hy);
                    __nv_bfloat162 lp(__float2bfloat16(x - __bfloat162float(hx)),
                                      __float2bfloat16(y - __bfloat162float(hy)));
                    ph[kk][half * 2 + hv] = *(uint32_t*)&hp;
                    pl[kk][half * 2 + hv] = *(uint32_t*)&lp;
                }
            }
        }

        // ---- PV: oacc += Phi*Vhi + Plo*Vhi + Phi*Vlo ----
#pragma unroll
        for (int kk = 0; kk < 4; kk++) {
            uint32_t bv[8][2];
#pragma unroll
            for (int np = 0; np < 4; np++) {
                uint32_t r0, r1, r2, r3;
                ldsm_x4_t(r0, r1, r2, r3,
                          VBh + ((kk * 16 + vrow) * ATT_T + 8 * (2 * np + vcolw)) * 2);
                bv[2 * np][0] = r0; bv[2 * np][1] = r1;
                bv[2 * np + 1][0] = r2; bv[2 * np + 1][1] = r3;
            }
#pragma unroll
            for (int ni = 0; ni < 8; ni++)
                mma_bf16(oacc[ni], ph[kk][0], ph[kk][1], ph[kk][2], ph[kk][3], bv[ni][0], bv[ni][1]);
#pragma unroll
            for (int ni = 0; ni < 8; ni++)
                mma_bf16(oacc[ni], pl[kk][0], pl[kk][1], pl[kk][2], pl[kk][3], bv[ni][0], bv[ni][1]);
            uint32_t bvl[8][2];
#pragma unroll
            for (int np = 0; np < 4; np++) {
                uint32_t r0, r1, r2, r3;
                ldsm_x4_t(r0, r1, r2, r3,
                          VBl + ((kk * 16 + vrow) * ATT_T + 8 * (2 * np + vcolw)) * 2);
                bvl[2 * np][0] = r0; bvl[2 * np][1] = r1;
                bvl[2 * np + 1][0] = r2; bvl[2 * np + 1][1] = r3;
            }
#pragma unroll
            for (int ni = 0; ni < 8; ni++)
                mma_bf16(oacc[ni], ph[kk][0], ph[kk][1], ph[kk][2], ph[kk][3], bvl[ni][0], bvl[ni][1]);
        }

        // ---- pipeline advance ----
        __syncthreads();
        if (kt + 2 < NT) {
            load_kv(kt & 1, kt + 2);
            CP_COMMIT();
            CP_WAIT(1);
            __syncthreads();
        } else if (kt + 1 < NT) {
            CP_WAIT(0);
            __syncthreads();
        }
    }

    // ---- epilogue ----
    float i0 = 1.0f / sl0, i1 = 1.0f / sl1;
    const int qrow = qt * 64 + w * 16;
#pragma unroll
    for (int ni = 0; ni < 8; ni++) {
        size_t base = ((size_t)(b * S + qrow + tr)) * D + (size_t)h * 64 + ni * 8 + tc * 2;
        float2 v0 = make_float2(oacc[ni][0] * i0, oacc[ni][1] * i0);
        float2 v1 = make_float2(oacc[ni][2] * i1, oacc[ni][3] * i1);
        *(float2*)(ctx + base) = v0;
        *(float2*)(ctx + base + (size_t)8 * D) = v1;
    }
}

// ---------------- launch ----------------
extern "C" void kernel_launch(void* const* d_in, const int* in_sizes, int n_in,
                              void* d_out, int out_size) {
    const float* key = (const float*)d_in[0];
    const float* query = (const float*)d_in[1];
    const float* value = (const float*)d_in[2];
    const float* Wq = (const float*)d_in[3];
    const float* Wk = (const float*)d_in[4];
    const float* Wv = (const float*)d_in[5];
    const float* Wo = (const float*)d_in[6];
    const float* bo = (const float*)d_in[7];

    const int B = 2;
    const int S = in_sizes[0] / (B * D);  // 2048
    const int M = B * S;                  // 4096
    const int nA = M * D;

    float* Cb;
    __nv_bfloat16 *Aq, *Ak, *Av, *Ac, *Wq2, *Wk2, *Wv2, *Wo2;
    __nv_bfloat16 *Qh, *Ql, *Kh, *Kl, *Vh, *Vl;
    cudaGetSymbolAddress((void**)&Cb, g_C);
    cudaGetSymbolAddress((void**)&Aq, g_Aq);
    cudaGetSymbolAddress((void**)&Ak, g_Ak);
    cudaGetSymbolAddress((void**)&Av, g_Av);
    cudaGetSymbolAddress((void**)&Ac, g_Ac);
    cudaGetSymbolAddress((void**)&Wq2, g_Wq2);
    cudaGetSymbolAddress((void**)&Wk2, g_Wk2);
    cudaGetSymbolAddress((void**)&Wv2, g_Wv2);
    cudaGetSymbolAddress((void**)&Wo2, g_Wo2);
    cudaGetSymbolAddress((void**)&Qh, g_Qhi);
    cudaGetSymbolAddress((void**)&Ql, g_Qlo);
    cudaGetSymbolAddress((void**)&Kh, g_Khi);
    cudaGetSymbolAddress((void**)&Kl, g_Klo);
    cudaGetSymbolAddress((void**)&Vh, g_Vhi);
    cudaGetSymbolAddress((void**)&Vl, g_Vlo);

    cudaFuncSetAttribute(gemm_mma, cudaFuncAttributeMaxDynamicSharedMemorySize, GSMEM);
    cudaFuncSetAttribute(attn_tc, cudaFuncAttributeMaxDynamicSharedMemorySize, ATT_SMEM);

    dim3 gG(D / 128, M / 128);  // (8, 32)

    split_all<<<16384, 256>>>(query, key, value, Wq, Wk, Wv, Wo,
                              Aq, Ak, Av, Wq2, Wk2, Wv2, Wo2);
    gemm_mma<<<gG, 256, GSMEM>>>(Aq, Wq2, nullptr, nullptr, Qh, Ql);
    gemm_mma<<<gG, 256, GSMEM>>>(Ak, Wk2, nullptr, nullptr, Kh, Kl);
    gemm_mma<<<gG, 256, GSMEM>>>(Av, Wv2, nullptr, nullptr, Vh, Vl);

    dim3 gAt(S / 64, HEADS, B);  // (32, 16, 2)
    attn_tc<<<gAt, 128, ATT_SMEM>>>(Qh, Ql, Kh, Kl, Vh, Vl, Cb, S);

    split3<<<nA / 1024, 256>>>(Cb, Ac, nA, 0);
    gemm_mma<<<gG, 256, GSMEM>>>(Ac, Wo2, bo, (float*)d_out, nullptr, nullptr);
}